// round 10
// baseline (speedup 1.0000x reference)
#include <cuda_runtime.h>
#include <math.h>

#define TT 512
#define BB 64
#define VV 256
#define EE 512
#define HH 512

#define GRID_REC 128
#define NTH 544            // 16 compute warps + 1 poller warp

#define WCOL  257          // ull2 stride per (d,col) weight column (padded, conflict-free)

typedef unsigned long long ull;
__device__ __forceinline__ ull pk2(float x, float y) {
    ull r; asm("mov.b64 %0,{%1,%2};" : "=l"(r) : "f"(x), "f"(y)); return r;
}
__device__ __forceinline__ ull pkd(float x) {
    ull r; asm("mov.b64 %0,{%1,%1};" : "=l"(r) : "f"(x)); return r;
}
__device__ __forceinline__ ull fma2(ull a, ull b, ull c) {
    ull d; asm("fma.rn.f32x2 %0,%1,%2,%3;" : "=l"(d) : "l"(a), "l"(b), "l"(c)); return d;
}
__device__ __forceinline__ ull add2(ull a, ull b) {
    ull d; asm("add.rn.f32x2 %0,%1,%2;" : "=l"(d) : "l"(a), "l"(b)); return d;
}
__device__ __forceinline__ float2 upk2(ull a) {
    float2 r; asm("mov.b64 {%0,%1},%2;" : "=f"(r.x), "=f"(r.y) : "l"(a)); return r;
}

// ---------------------------------------------------------------------------
__device__ float g_table_t[2 * HH * VV];          // [j][v] : (emb @ w_in[0])^T
__device__ float g_stateA[BB * HH];               // state ping [b][k]
__device__ float g_stateB[BB * HH];               // state pong [b][k]
__device__ float g_out0[TT][HH * BB];             // layer-0 outputs [t][h][b]
__device__ float g_out1[TT][HH * BB];             // layer-1 outputs [t][h][b]
__device__ float g_in1[TT][2 * HH * BB];          // layer-1 input preact [t][j][b]
__device__ unsigned g_bcnt[2 * 8 * 32];           // per-rowgroup, per-chunk counters

__global__ void k_reset() {
    int idx = blockIdx.x * blockDim.x + threadIdx.x;
    if (idx < 2 * 8 * 32) g_bcnt[idx] = 0u;
}

__global__ void k_zero() {
    int idx = blockIdx.x * blockDim.x + threadIdx.x;
    if (idx < BB * HH) g_stateA[idx] = 0.0f;
}

// ---------------------------------------------------------------------------
__global__ void k_table(const float* __restrict__ emb,
                        const float* __restrict__ w_in) {
    int v = blockIdx.x;
    int j = threadIdx.x * 4;
    const float* er = emb + v * EE;
    float4 acc = make_float4(0.f, 0.f, 0.f, 0.f);
#pragma unroll 4
    for (int e = 0; e < EE; ++e) {
        float ev = er[e];
        float4 wv = *reinterpret_cast<const float4*>(w_in + (size_t)e * (2 * HH) + j);
        acc.x = fmaf(ev, wv.x, acc.x);
        acc.y = fmaf(ev, wv.y, acc.y);
        acc.z = fmaf(ev, wv.z, acc.z);
        acc.w = fmaf(ev, wv.w, acc.w);
    }
    g_table_t[(j + 0) * VV + v] = acc.x;
    g_table_t[(j + 1) * VV + v] = acc.y;
    g_table_t[(j + 2) * VV + v] = acc.z;
    g_table_t[(j + 3) * VV + v] = acc.w;
}

// ---------------------------------------------------------------------------
// Persistent RHN pass, chunk-pipelined exchange.
// 128 CTAs = 2 rowgroups x 64 colgroups. 17 warps: 16 compute (4 rows x 8
// cols, k split in 2), 1 poller. H split into 8 chunks of 64 k; producers
// red.release a chunk counter; poller publishes SMEM ready flags; compute
// warps gate each 16-iter chunk on the flag, reading state from L2 (__ldcg).
// Exchange latency hides behind compute of earlier chunks.
// ---------------------------------------------------------------------------
template <int PASS>
__global__ void __launch_bounds__(NTH, 1) k_rhn(
    const int*   __restrict__ x,
    const float* __restrict__ w_h,
    const float* __restrict__ b_h)
{
    extern __shared__ float smraw[];
    ulonglong2* w_pk    = reinterpret_cast<ulonglong2*>(smraw);          // 131584 B
    float2*     scratch = reinterpret_cast<float2*>(smraw + 32896);      // 2048 B
    __shared__ volatile int s_ready[8];                                   // chunk flags

    const int tid   = threadIdx.x;
    const int cid   = blockIdx.x;
    const int rg    = cid >> 6;
    const int cg    = cid & 63;
    const int w     = tid >> 5;
    const int lane  = tid & 31;
    const int rr    = lane >> 3;
    const int c     = lane & 7;
    const int wq    = w & 7;
    const int khalf = w >> 3;           // 2 for poller warp (unused there)
    const int lrow  = wq * 4 + rr;
    const int grow  = rg * 32 + lrow;
    const int scol  = cg * 8 + c;

    // ---- stage weights (h,g,k-pair packed, padded) ----
    for (int idx = tid; idx < 4 * 256 * 8; idx += NTH) {
        int cp = idx & 7;
        int kp = (idx >> 3) & 255;
        int d  = idx >> 11;
        const float* b0 = w_h + (((size_t)(PASS * 4 + d) * HH + 2 * kp) * (2 * HH)) + cg * 8 + cp;
        const float* b1 = b0 + 2 * HH;
        w_pk[(d * 8 + cp) * WCOL + kp] =
            make_ulonglong2(pk2(b0[0], b1[0]), pk2(b0[HH], b1[HH]));
    }
    if (tid < 8) s_ready[tid] = 0;

    float bh[4], bg[4];
#pragma unroll
    for (int d = 0; d < 4; ++d) {
        bh[d] = b_h[(size_t)(PASS * 4 + d) * (2 * HH) + scol];
        bg[d] = b_h[(size_t)(PASS * 4 + d) * (2 * HH) + HH + scol];
    }
    __syncthreads();    // all 17 warps: weights + flags ready

    unsigned* cntbase = (unsigned*)&g_bcnt[rg * 8 * 32];
    const unsigned pbase = (unsigned)PASS * 2048u;

    // ================= poller warp: free-running flag publisher =============
    if (w == 16) {
        if (lane < 8) {
            unsigned* cp_ = cntbase + lane * 32;
            for (int s = 1; s <= 2047; ++s) {
                unsigned tgt = 8u * (pbase + (unsigned)s);
                unsigned v;
                do {
                    asm volatile("ld.acquire.gpu.global.u32 %0,[%1];"
                                 : "=r"(v) : "l"(cp_) : "memory");
                } while (v < tgt);
                __threadfence_block();
                s_ready[lane] = s;
            }
        }
        return;
    }

    // ================= compute warps ========================================
    unsigned* my_cnt = cntbase + ((cg >> 3) * 32);

    const float* s_cur = g_stateA;
    float*       s_nxt = g_stateB;

    // prefetch t=0 input (khalf0 consumes it)
    float2 inp_cur = make_float2(0.f, 0.f);
    if (khalf == 0) {
        if (PASS == 0) {
            int xv = x[0 * BB + grow];
            inp_cur = make_float2(g_table_t[(size_t)scol * VV + xv],
                                  g_table_t[(size_t)(HH + scol) * VV + xv]);
        } else {
            inp_cur = make_float2(__ldcg(&g_in1[0][scol * BB + grow]),
                                  __ldcg(&g_in1[0][(HH + scol) * BB + grow]));
        }
    }

    int sidx = 0;
    for (int t = 0; t < TT; ++t) {
        float2 inp_next = make_float2(0.f, 0.f);
        for (int d = 0; d < 4; ++d) {
            // prefetch next-t input early (overlaps with dot)
            if (d == 0 && khalf == 0 && t + 1 < TT) {
                if (PASS == 0) {
                    int xv = x[(t + 1) * BB + grow];
                    inp_next = make_float2(g_table_t[(size_t)scol * VV + xv],
                                           g_table_t[(size_t)(HH + scol) * VV + xv]);
                } else {
                    inp_next = make_float2(__ldcg(&g_in1[t + 1][scol * BB + grow]),
                                           __ldcg(&g_in1[t + 1][(HH + scol) * BB + grow]));
                }
            }

            // ---- chunk-gated k-dot: state straight from L2, weights SMEM ----
            ull ah0 = pk2(0.f, 0.f), ag0 = pk2(0.f, 0.f);
            ull ah1 = pk2(0.f, 0.f), ag1 = pk2(0.f, 0.f);
            const ulonglong2* wp = w_pk + (size_t)(d * 8 + c) * WCOL;
            const float* srow = s_cur + (size_t)grow * HH;

#pragma unroll
            for (int ch = 0; ch < 4; ++ch) {
                const int gch = khalf * 4 + ch;
                if (lane == 0 && sidx > 0) {
                    while (s_ready[gch] < sidx) { }
                    __threadfence_block();
                }
                __syncwarp();
                const float4* sp = reinterpret_cast<const float4*>(srow + gch * 64);
#pragma unroll
                for (int q = 0; q < 16; ++q) {
                    float4 s4 = __ldcg(sp + q);          // k: gch*64+4q..+3
                    ull sv0 = pk2(s4.x, s4.y);
                    ull sv1 = pk2(s4.z, s4.w);
                    int kp = gch * 32 + 2 * q;
                    ulonglong2 wA = wp[kp];
                    ulonglong2 wB = wp[kp + 1];
                    ah0 = fma2(sv0, wA.x, ah0);
                    ag0 = fma2(sv0, wA.y, ag0);
                    ah1 = fma2(sv1, wB.x, ah1);
                    ag1 = fma2(sv1, wB.y, ag1);
                }
            }
            float2 hp = upk2(add2(ah0, ah1));
            float2 gp = upk2(add2(ag0, ag1));
            float h_part = hp.x + hp.y;
            float g_part = gp.x + gp.y;

            if (khalf == 1) scratch[lrow * 8 + c] = make_float2(h_part, g_part);
            asm volatile("bar.sync 1, 512;" ::: "memory");

            if (khalf == 0) {
                float2 o = scratch[lrow * 8 + c];
                float acc_h = bh[d] + h_part + o.x;
                float acc_g = bg[d] + g_part + o.y;
                if (d == 0) { acc_h += inp_cur.x; acc_g += inp_cur.y; }

                float s_old = __ldcg(&srow[scol]);
                float gt = 1.0f / (1.0f + expf(-acc_g));
                float ht = tanhf(acc_h);
                float s_new = ht * gt + s_old * (1.0f - gt);

                __stcg(&s_nxt[(size_t)grow * HH + scol], s_new);
                if (d == 3) {
                    float* ob = (PASS == 0) ? g_out0[t] : g_out1[t];
                    ob[scol * BB + grow] = s_new;
                }
                __threadfence();                 // order state STGs (gpu scope)
            }

            asm volatile("bar.sync 1, 512;" ::: "memory");
            if (tid == 0) {
                asm volatile("red.release.gpu.global.add.u32 [%0], 1;"
                             :: "l"(my_cnt) : "memory");
            }

            const float* tmp = s_nxt;
            s_nxt = (float*)s_cur;
            s_cur = tmp;
            ++sidx;
        }
        inp_cur = inp_next;
    }
}

// ---------------------------------------------------------------------------
// g_in1[t][j][b] = sum_h g_out0[t][h][b] * w_in[1][h][j]   (FFMA2)
// ---------------------------------------------------------------------------
__global__ void k_inp1(const float* __restrict__ w_in) {
    int bid = blockIdx.x;
    int t   = bid >> 4;
    int jb  = bid & 15;
    int tid = threadIdx.x;
    int b   = tid & 63;
    int js  = tid >> 6;
    int j0  = jb * 64 + js * 16;

    ull acc[8];
#pragma unroll
    for (int i = 0; i < 8; ++i) acc[i] = pk2(0.f, 0.f);

    const float* o  = g_out0[t];
    const float* w1 = w_in + (size_t)EE * (2 * HH);
#pragma unroll 2
    for (int h = 0; h < HH; ++h) {
        ull svp = pkd(o[h * BB + b]);
        const ulonglong2* wr = reinterpret_cast<const ulonglong2*>(w1 + (size_t)h * (2 * HH) + j0);
        ulonglong2 q0 = wr[0], q1 = wr[1], q2 = wr[2], q3 = wr[3];
        acc[0] = fma2(svp, q0.x, acc[0]);  acc[1] = fma2(svp, q0.y, acc[1]);
        acc[2] = fma2(svp, q1.x, acc[2]);  acc[3] = fma2(svp, q1.y, acc[3]);
        acc[4] = fma2(svp, q2.x, acc[4]);  acc[5] = fma2(svp, q2.y, acc[5]);
        acc[6] = fma2(svp, q3.x, acc[6]);  acc[7] = fma2(svp, q3.y, acc[7]);
    }
#pragma unroll
    for (int i = 0; i < 8; ++i) {
        float2 v = upk2(acc[i]);
        g_in1[t][(j0 + 2 * i) * BB + b]     = v.x;
        g_in1[t][(j0 + 2 * i + 1) * BB + b] = v.y;
    }
}

// ---------------------------------------------------------------------------
__global__ void k_logits(const float* __restrict__ w_fc,
                         const float* __restrict__ b_fc,
                         float* __restrict__ out) {
    int bid = blockIdx.x;
    int t   = bid >> 2;
    int vb  = bid & 3;
    int tid = threadIdx.x;
    int b   = tid & 63;
    int vs  = tid >> 6;
    int v0  = vb * 64 + vs * 16;

    ull acc[8];
    const ulonglong2* bp = reinterpret_cast<const ulonglong2*>(b_fc + v0);
#pragma unroll
    for (int i = 0; i < 4; ++i) {
        ulonglong2 bq = bp[i];
        acc[2 * i] = bq.x; acc[2 * i + 1] = bq.y;
    }

    const float* o = g_out1[t];
#pragma unroll 2
    for (int h = 0; h < HH; ++h) {
        ull svp = pkd(o[h * BB + b]);
        const ulonglong2* wr = reinterpret_cast<const ulonglong2*>(w_fc + (size_t)h * VV + v0);
        ulonglong2 q0 = wr[0], q1 = wr[1], q2 = wr[2], q3 = wr[3];
        acc[0] = fma2(svp, q0.x, acc[0]);  acc[1] = fma2(svp, q0.y, acc[1]);
        acc[2] = fma2(svp, q1.x, acc[2]);  acc[3] = fma2(svp, q1.y, acc[3]);
        acc[4] = fma2(svp, q2.x, acc[4]);  acc[5] = fma2(svp, q2.y, acc[5]);
        acc[6] = fma2(svp, q3.x, acc[6]);  acc[7] = fma2(svp, q3.y, acc[7]);
    }

    ull* dst = reinterpret_cast<ull*>(out + ((size_t)(t * BB + b)) * VV + v0);
#pragma unroll
    for (int i = 0; i < 8; ++i) dst[i] = acc[i];
}

// ---------------------------------------------------------------------------
__global__ void k_sfinal(float* __restrict__ out, int l) {
    int idx = blockIdx.x * blockDim.x + threadIdx.x;
    if (idx >= BB * HH) return;
    out[(size_t)TT * BB * VV + (size_t)l * BB * HH + idx] = g_stateA[idx];
}

// ---------------------------------------------------------------------------
extern "C" void kernel_launch(void* const* d_in, const int* in_sizes, int n_in,
                              void* d_out, int out_size) {
    const int*   x    = (const int*)  d_in[0];
    const float* emb  = (const float*)d_in[1];
    const float* w_in = (const float*)d_in[2];
    const float* w_h  = (const float*)d_in[3];
    const float* b_h  = (const float*)d_in[4];
    const float* w_fc = (const float*)d_in[5];
    const float* b_fc = (const float*)d_in[6];
    float* out = (float*)d_out;

    // 131584 (weights) + 2048 (scratch) = 133632 B dynamic smem
    const int smem_bytes = 131584 + 2048;
    static bool attr_done = false;
    if (!attr_done) {
        cudaFuncSetAttribute(k_rhn<0>, cudaFuncAttributeMaxDynamicSharedMemorySize, smem_bytes);
        cudaFuncSetAttribute(k_rhn<1>, cudaFuncAttributeMaxDynamicSharedMemorySize, smem_bytes);
        attr_done = true;
    }

    const bool has_sfinal = (out_size >= TT * BB * VV + 2 * BB * HH);

    k_reset<<<2, 256>>>();                                              // 1
    k_table<<<VV, 256>>>(emb, w_in);                                    // 2
    k_zero<<<(BB * HH + 255) / 256, 256>>>();                           // 3
    k_rhn<0><<<GRID_REC, NTH, smem_bytes>>>(x, w_h, b_h);               // 4 <- profiled
    if (has_sfinal)
        k_sfinal<<<(BB * HH + 255) / 256, 256>>>(out, 0);
    k_inp1<<<TT * 16, 256>>>(w_in);
    k_zero<<<(BB * HH + 255) / 256, 256>>>();
    k_rhn<1><<<GRID_REC, NTH, smem_bytes>>>(x, w_h, b_h);
    k_logits<<<TT * 4, 256>>>(w_fc, b_fc, out);
    if (has_sfinal)
        k_sfinal<<<(BB * HH + 255) / 256, 256>>>(out, 1);
}

// round 11
// speedup vs baseline: 1.8052x; 1.8052x over previous
#include <cuda_runtime.h>
#include <math.h>

#define TT 512
#define BB 64
#define VV 256
#define EE 512
#define HH 512

#define GRID_REC 128
#define NTH 256

typedef unsigned long long ull;
__device__ __forceinline__ ull pk2(float x, float y) {
    ull r; asm("mov.b64 %0,{%1,%2};" : "=l"(r) : "f"(x), "f"(y)); return r;
}
__device__ __forceinline__ ull pkd(float x) {
    ull r; asm("mov.b64 %0,{%1,%1};" : "=l"(r) : "f"(x)); return r;
}
__device__ __forceinline__ ull fma2(ull a, ull b, ull c) {
    ull d; asm("fma.rn.f32x2 %0,%1,%2,%3;" : "=l"(d) : "l"(a), "l"(b), "l"(c)); return d;
}
__device__ __forceinline__ ull add2(ull a, ull b) {
    ull d; asm("add.rn.f32x2 %0,%1,%2;" : "=l"(d) : "l"(a), "l"(b)); return d;
}
__device__ __forceinline__ float2 upk2(ull a) {
    float2 r; asm("mov.b64 {%0,%1},%2;" : "=f"(r.x), "=f"(r.y) : "l"(a)); return r;
}

// ---------------------------------------------------------------------------
// Static scratch.  State layout: [kp][b][2]  (k-pair interleaved, kp=h>>1)
// ---------------------------------------------------------------------------
__device__ float g_table_t[2 * HH * VV];          // [j][v] : (emb @ w_in[0])^T
__device__ float g_stateA[256 * BB * 2];          // state ping [kp][b][2]
__device__ float g_stateB[256 * BB * 2];          // state pong [kp][b][2]
__device__ float g_out0[TT][HH * BB];             // layer-0 outputs [t][h][b]
__device__ float g_out1[TT][HH * BB];             // layer-1 outputs [t][h][b]
__device__ float g_in1[TT][2 * HH * BB];          // layer-1 input preact [t][j][b]
__device__ volatile unsigned g_flags[GRID_REC * 32];
__device__ volatile unsigned g_phase[2 * 32];

__global__ void k_reset() {
    int idx = blockIdx.x * blockDim.x + threadIdx.x;
    if (idx < GRID_REC * 32) g_flags[idx] = 0u;
    if (idx < 2 * 32) g_phase[idx] = 0u;
}

__global__ void k_zero() {
    int idx = blockIdx.x * blockDim.x + threadIdx.x;
    if (idx < 256 * BB * 2) g_stateA[idx] = 0.0f;
}

// ---------------------------------------------------------------------------
__global__ void k_table(const float* __restrict__ emb,
                        const float* __restrict__ w_in) {
    int v = blockIdx.x;
    int j = threadIdx.x * 4;
    const float* er = emb + v * EE;
    float4 acc = make_float4(0.f, 0.f, 0.f, 0.f);
#pragma unroll 4
    for (int e = 0; e < EE; ++e) {
        float ev = er[e];
        float4 wv = *reinterpret_cast<const float4*>(w_in + (size_t)e * (2 * HH) + j);
        acc.x = fmaf(ev, wv.x, acc.x);
        acc.y = fmaf(ev, wv.y, acc.y);
        acc.z = fmaf(ev, wv.z, acc.z);
        acc.w = fmaf(ev, wv.w, acc.w);
    }
    g_table_t[(j + 0) * VV + v] = acc.x;
    g_table_t[(j + 1) * VV + v] = acc.y;
    g_table_t[(j + 2) * VV + v] = acc.z;
    g_table_t[(j + 3) * VV + v] = acc.w;
}

// ---------------------------------------------------------------------------
// Rowgroup barrier: master CTA (cid = rg<<6) gathers 63 member flags,
// releases one phase word. R2-proven structure, split into 2 domains.
// ---------------------------------------------------------------------------
__device__ __forceinline__ void gbar(int rg, int cid, int tid, unsigned epoch) {
    __threadfence();
    __syncthreads();
    if (cid == (rg << 6)) {
        if (tid >= 1 && tid < 64) {
            while (g_flags[((rg << 6) + tid) * 32] < epoch) { }
        }
        __syncthreads();
        if (tid == 0) {
            __threadfence();
            g_phase[rg * 32] = epoch;
        }
    } else {
        if (tid == 0) {
            g_flags[cid * 32] = epoch;
            while (g_phase[rg * 32] < epoch) { }
            __threadfence();
        }
    }
    __syncthreads();
}

// ---------------------------------------------------------------------------
// Persistent RHN pass. 128 CTAs = 2 rowgroups x 64 colgroups.
// CTA: 32 rows x 8 cols. 256 thr, warp = 32 rows x 2 cols x khalf:
//   w = tid>>5: cpq = w&3 (col pair-of-pairs), khalf = w>>2; lane = row.
// State in SMEM as float2 (s_2kp, s_2kp+1) -> LDS.64 = FFMA2 operand directly.
// Weights SMEM ull2 {(wh_k0,wh_k1),(wg_k0,wg_k1)} broadcast loads.
// ---------------------------------------------------------------------------
template <int PASS>
__global__ void __launch_bounds__(NTH, 1) k_rhn(
    const int*   __restrict__ x,
    const float* __restrict__ w_h,
    const float* __restrict__ b_h)
{
    extern __shared__ float smraw[];
    ulonglong2* w_pk    = reinterpret_cast<ulonglong2*>(smraw);          // [4][8][256] 131072 B
    float2*     s_pair  = reinterpret_cast<float2*>(smraw + 32768);      // [256][32]    65536 B
    float2*     scratch = reinterpret_cast<float2*>(smraw + 49152);      // [8][32]       2048 B

    const int tid   = threadIdx.x;
    const int cid   = blockIdx.x;
    const int rg    = cid >> 6;
    const int cg    = cid & 63;
    const int w     = tid >> 5;
    const int lane  = tid & 31;
    const int cpq   = w & 3;            // handles CTA-local cols 2cpq, 2cpq+1
    const int khalf = w >> 2;
    const int r     = lane;             // local row
    const int grow  = rg * 32 + r;
    const int j0    = cg * 8 + 2 * cpq; // global col (even)
    const int kpj   = cg * 4 + cpq;     // global kp of this thread's col pair

    // ---- stage weights: w_pk[(d*8+cp)*256 + kp] = {(wh0,wh1),(wg0,wg1)} ----
    for (int idx = tid; idx < 4 * 8 * 256; idx += NTH) {
        int cp = idx & 7;
        int kp = (idx >> 3) & 255;
        int d  = idx >> 11;
        const float* b0 = w_h + (((size_t)(PASS * 4 + d) * HH + 2 * kp) * (2 * HH)) + cg * 8 + cp;
        const float* b1 = b0 + 2 * HH;
        w_pk[(d * 8 + cp) * 256 + kp] =
            make_ulonglong2(pk2(b0[0], b1[0]), pk2(b0[HH], b1[HH]));
    }

    float bh0[4], bg0[4], bh1[4], bg1[4];
#pragma unroll
    for (int d = 0; d < 4; ++d) {
        const float* bb = b_h + (size_t)(PASS * 4 + d) * (2 * HH);
        bh0[d] = bb[j0];      bg0[d] = bb[HH + j0];
        bh1[d] = bb[j0 + 1];  bg1[d] = bb[HH + j0 + 1];
    }
    __syncthreads();

    const float* s_cur = g_stateA;
    float*       s_nxt = g_stateB;
    const unsigned pbase = (unsigned)PASS * 2048u;

    const ull* sp = reinterpret_cast<const ull*>(s_pair) + khalf * 128 * 32 + r;

    // prefetch t=0 input (khalf0 consumes it)
    float4 inp_cur = make_float4(0.f, 0.f, 0.f, 0.f);
    if (khalf == 0) {
        if (PASS == 0) {
            int xv = x[0 * BB + grow];
            inp_cur = make_float4(g_table_t[(size_t)j0 * VV + xv],
                                  g_table_t[(size_t)(HH + j0) * VV + xv],
                                  g_table_t[(size_t)(j0 + 1) * VV + xv],
                                  g_table_t[(size_t)(HH + j0 + 1) * VV + xv]);
        } else {
            inp_cur = make_float4(__ldcg(&g_in1[0][j0 * BB + grow]),
                                  __ldcg(&g_in1[0][(HH + j0) * BB + grow]),
                                  __ldcg(&g_in1[0][(j0 + 1) * BB + grow]),
                                  __ldcg(&g_in1[0][(HH + j0 + 1) * BB + grow]));
        }
    }

    unsigned sidx = 0;
    for (int t = 0; t < TT; ++t) {
        float4 inp_next = make_float4(0.f, 0.f, 0.f, 0.f);
        for (int d = 0; d < 4; ++d) {
            // ---- stage state tile: 64KB dense .cg copy into s_pair[kp][32] ----
            // global slice per kp: 256B at kp*512B + rg*256B (contiguous)
#pragma unroll
            for (int i2 = 0; i2 < 16; ++i2) {
                int idx = tid + i2 * NTH;           // 0..4095
                int kp = idx >> 4, i = idx & 15;
                reinterpret_cast<float4*>(s_pair)[kp * 16 + i] =
                    __ldcg(reinterpret_cast<const float4*>(
                        s_cur + (size_t)kp * 128 + rg * 64) + i);
            }
            __syncthreads();

            // prefetch next-t input during compute
            if (d == 0 && khalf == 0 && t + 1 < TT) {
                if (PASS == 0) {
                    int xv = x[(t + 1) * BB + grow];
                    inp_next = make_float4(g_table_t[(size_t)j0 * VV + xv],
                                           g_table_t[(size_t)(HH + j0) * VV + xv],
                                           g_table_t[(size_t)(j0 + 1) * VV + xv],
                                           g_table_t[(size_t)(HH + j0 + 1) * VV + xv]);
                } else {
                    inp_next = make_float4(__ldcg(&g_in1[t + 1][j0 * BB + grow]),
                                           __ldcg(&g_in1[t + 1][(HH + j0) * BB + grow]),
                                           __ldcg(&g_in1[t + 1][(j0 + 1) * BB + grow]),
                                           __ldcg(&g_in1[t + 1][(HH + j0 + 1) * BB + grow]));
                }
            }

            // ---- packed k-pair dot over this khalf (128 kp), 2 cols ----
            ull ah0 = pk2(0.f, 0.f), ag0 = pk2(0.f, 0.f);
            ull ah1 = pk2(0.f, 0.f), ag1 = pk2(0.f, 0.f);
            const ulonglong2* wp0 = w_pk + (size_t)(d * 8 + 2 * cpq) * 256 + khalf * 128;
            const ulonglong2* wp1 = wp0 + 256;
#pragma unroll 8
            for (int q = 0; q < 128; ++q) {
                ull sv = sp[q * 32];                // (s_k0, s_k1) pre-packed
                ulonglong2 w0 = wp0[q];
                ulonglong2 w1 = wp1[q];
                ah0 = fma2(sv, w0.x, ah0);
                ag0 = fma2(sv, w0.y, ag0);
                ah1 = fma2(sv, w1.x, ah1);
                ag1 = fma2(sv, w1.y, ag1);
            }
            float2 h0p = upk2(ah0), g0p = upk2(ag0);
            float2 h1p = upk2(ah1), g1p = upk2(ag1);

            if (khalf == 1) {
                scratch[(cpq * 2 + 0) * 32 + r] = make_float2(h0p.x + h0p.y, g0p.x + g0p.y);
                scratch[(cpq * 2 + 1) * 32 + r] = make_float2(h1p.x + h1p.y, g1p.x + g1p.y);
            }
            __syncthreads();

            if (khalf == 0) {
                float2 o0 = scratch[(cpq * 2 + 0) * 32 + r];
                float2 o1 = scratch[(cpq * 2 + 1) * 32 + r];
                float acc_h0 = bh0[d] + h0p.x + h0p.y + o0.x;
                float acc_g0 = bg0[d] + g0p.x + g0p.y + o0.y;
                float acc_h1 = bh1[d] + h1p.x + h1p.y + o1.x;
                float acc_g1 = bg1[d] + g1p.x + g1p.y + o1.y;
                if (d == 0) {
                    acc_h0 += inp_cur.x; acc_g0 += inp_cur.y;
                    acc_h1 += inp_cur.z; acc_g1 += inp_cur.w;
                }

                float2 so = s_pair[kpj * 32 + r];   // (s_old_even, s_old_odd)
                float gt0 = 1.0f / (1.0f + expf(-acc_g0));
                float gt1 = 1.0f / (1.0f + expf(-acc_g1));
                float ht0 = tanhf(acc_h0);
                float ht1 = tanhf(acc_h1);
                float sn0 = ht0 * gt0 + so.x * (1.0f - gt0);
                float sn1 = ht1 * gt1 + so.y * (1.0f - gt1);

                // one vector store: state pair [kpj][grow]
                __stcg(reinterpret_cast<float2*>(s_nxt) + kpj * BB + grow,
                       make_float2(sn0, sn1));
                if (d == 3) {
                    float* ob = (PASS == 0) ? g_out0[t] : g_out1[t];
                    ob[j0 * BB + grow]       = sn0;
                    ob[(j0 + 1) * BB + grow] = sn1;
                }
            }

            ++sidx;
            gbar(rg, cid, tid, pbase + sidx);

            const float* tmp = s_nxt;
            s_nxt = (float*)s_cur;
            s_cur = tmp;
        }
        inp_cur = inp_next;
    }
}

// ---------------------------------------------------------------------------
// g_in1[t][j][b] = sum_h g_out0[t][h][b] * w_in[1][h][j]   (FFMA2)
// ---------------------------------------------------------------------------
__global__ void k_inp1(const float* __restrict__ w_in) {
    int bid = blockIdx.x;
    int t   = bid >> 4;
    int jb  = bid & 15;
    int tid = threadIdx.x;
    int b   = tid & 63;
    int js  = tid >> 6;
    int j0  = jb * 64 + js * 16;

    ull acc[8];
#pragma unroll
    for (int i = 0; i < 8; ++i) acc[i] = pk2(0.f, 0.f);

    const float* o  = g_out0[t];
    const float* w1 = w_in + (size_t)EE * (2 * HH);
#pragma unroll 2
    for (int h = 0; h < HH; ++h) {
        ull svp = pkd(o[h * BB + b]);
        const ulonglong2* wr = reinterpret_cast<const ulonglong2*>(w1 + (size_t)h * (2 * HH) + j0);
        ulonglong2 q0 = wr[0], q1 = wr[1], q2 = wr[2], q3 = wr[3];
        acc[0] = fma2(svp, q0.x, acc[0]);  acc[1] = fma2(svp, q0.y, acc[1]);
        acc[2] = fma2(svp, q1.x, acc[2]);  acc[3] = fma2(svp, q1.y, acc[3]);
        acc[4] = fma2(svp, q2.x, acc[4]);  acc[5] = fma2(svp, q2.y, acc[5]);
        acc[6] = fma2(svp, q3.x, acc[6]);  acc[7] = fma2(svp, q3.y, acc[7]);
    }
#pragma unroll
    for (int i = 0; i < 8; ++i) {
        float2 v = upk2(acc[i]);
        g_in1[t][(j0 + 2 * i) * BB + b]     = v.x;
        g_in1[t][(j0 + 2 * i + 1) * BB + b] = v.y;
    }
}

// ---------------------------------------------------------------------------
__global__ void k_logits(const float* __restrict__ w_fc,
                         const float* __restrict__ b_fc,
                         float* __restrict__ out) {
    int bid = blockIdx.x;
    int t   = bid >> 2;
    int vb  = bid & 3;
    int tid = threadIdx.x;
    int b   = tid & 63;
    int vs  = tid >> 6;
    int v0  = vb * 64 + vs * 16;

    ull acc[8];
    const ulonglong2* bp = reinterpret_cast<const ulonglong2*>(b_fc + v0);
#pragma unroll
    for (int i = 0; i < 4; ++i) {
        ulonglong2 bq = bp[i];
        acc[2 * i] = bq.x; acc[2 * i + 1] = bq.y;
    }

    const float* o = g_out1[t];
#pragma unroll 2
    for (int h = 0; h < HH; ++h) {
        ull svp = pkd(o[h * BB + b]);
        const ulonglong2* wr = reinterpret_cast<const ulonglong2*>(w_fc + (size_t)h * VV + v0);
        ulonglong2 q0 = wr[0], q1 = wr[1], q2 = wr[2], q3 = wr[3];
        acc[0] = fma2(svp, q0.x, acc[0]);  acc[1] = fma2(svp, q0.y, acc[1]);
        acc[2] = fma2(svp, q1.x, acc[2]);  acc[3] = fma2(svp, q1.y, acc[3]);
        acc[4] = fma2(svp, q2.x, acc[4]);  acc[5] = fma2(svp, q2.y, acc[5]);
        acc[6] = fma2(svp, q3.x, acc[6]);  acc[7] = fma2(svp, q3.y, acc[7]);
    }

    ull* dst = reinterpret_cast<ull*>(out + ((size_t)(t * BB + b)) * VV + v0);
#pragma unroll
    for (int i = 0; i < 8; ++i) dst[i] = acc[i];
}

// ---------------------------------------------------------------------------
// s_final[l][b][h] from g_stateA in [kp][b][2] layout
// ---------------------------------------------------------------------------
__global__ void k_sfinal(float* __restrict__ out, int l) {
    int idx = blockIdx.x * blockDim.x + threadIdx.x;
    if (idx >= BB * HH) return;
    int b = idx >> 9;
    int h = idx & 511;
    out[(size_t)TT * BB * VV + (size_t)l * BB * HH + idx] =
        g_stateA[(h >> 1) * 128 + b * 2 + (h & 1)];
}

// ---------------------------------------------------------------------------
extern "C" void kernel_launch(void* const* d_in, const int* in_sizes, int n_in,
                              void* d_out, int out_size) {
    const int*   x    = (const int*)  d_in[0];
    const float* emb  = (const float*)d_in[1];
    const float* w_in = (const float*)d_in[2];
    const float* w_h  = (const float*)d_in[3];
    const float* b_h  = (const float*)d_in[4];
    const float* w_fc = (const float*)d_in[5];
    const float* b_fc = (const float*)d_in[6];
    float* out = (float*)d_out;

    const int smem_bytes = 131072 + 65536 + 2048;   // 198656 B
    static bool attr_done = false;
    if (!attr_done) {
        cudaFuncSetAttribute(k_rhn<0>, cudaFuncAttributeMaxDynamicSharedMemorySize, smem_bytes);
        cudaFuncSetAttribute(k_rhn<1>, cudaFuncAttributeMaxDynamicSharedMemorySize, smem_bytes);
        attr_done = true;
    }

    const bool has_sfinal = (out_size >= TT * BB * VV + 2 * BB * HH);

    k_reset<<<(GRID_REC * 32 + 255) / 256, 256>>>();                    // 1
    k_table<<<VV, 256>>>(emb, w_in);                                    // 2
    k_zero<<<(256 * BB * 2 + 255) / 256, 256>>>();                      // 3
    k_rhn<0><<<GRID_REC, NTH, smem_bytes>>>(x, w_h, b_h);               // 4 <- profiled
    if (has_sfinal)
        k_sfinal<<<(BB * HH + 255) / 256, 256>>>(out, 0);
    k_inp1<<<TT * 16, 256>>>(w_in);
    k_zero<<<(256 * BB * 2 + 255) / 256, 256>>>();
    k_rhn<1><<<GRID_REC, NTH, smem_bytes>>>(x, w_h, b_h);
    k_logits<<<TT * 4, 256>>>(w_fc, b_fc, out);
    if (has_sfinal)
        k_sfinal<<<(BB * HH + 255) / 256, 256>>>(out, 1);
}

// round 12
// speedup vs baseline: 1.9738x; 1.0934x over previous
#include <cuda_runtime.h>
#include <math.h>

#define TT 512
#define BB 64
#define VV 256
#define EE 512
#define HH 512

#define GRID_REC 128
#define NTH 256

typedef unsigned long long ull;
__device__ __forceinline__ ull pk2(float x, float y) {
    ull r; asm("mov.b64 %0,{%1,%2};" : "=l"(r) : "f"(x), "f"(y)); return r;
}
__device__ __forceinline__ ull pkd(float x) {
    ull r; asm("mov.b64 %0,{%1,%1};" : "=l"(r) : "f"(x)); return r;
}
__device__ __forceinline__ ull fma2(ull a, ull b, ull c) {
    ull d; asm("fma.rn.f32x2 %0,%1,%2,%3;" : "=l"(d) : "l"(a), "l"(b), "l"(c)); return d;
}
__device__ __forceinline__ ull add2(ull a, ull b) {
    ull d; asm("add.rn.f32x2 %0,%1,%2;" : "=l"(d) : "l"(a), "l"(b)); return d;
}
__device__ __forceinline__ float2 upk2(ull a) {
    float2 r; asm("mov.b64 {%0,%1},%2;" : "=f"(r.x), "=f"(r.y) : "l"(a)); return r;
}

// ---------------------------------------------------------------------------
// Static scratch.  State layout: [kp][b][2]  (k-pair interleaved, kp=h>>1)
// ---------------------------------------------------------------------------
__device__ float g_table_t[2 * HH * VV];          // [j][v] : (emb @ w_in[0])^T
__device__ float g_stateA[256 * BB * 2];          // state ping [kp][b][2]
__device__ float g_stateB[256 * BB * 2];          // state pong [kp][b][2]
__device__ float g_out0[TT][HH * BB];             // layer-0 outputs [t][h][b]
__device__ float g_out1[TT][HH * BB];             // layer-1 outputs [t][h][b]
__device__ float g_in1[TT][2 * HH * BB];          // layer-1 input preact [t][j][b]
__device__ unsigned g_cnt[2 * 2 * 4 * 32];        // [rg][half][sub] spread counters

__global__ void k_reset() {
    int idx = blockIdx.x * blockDim.x + threadIdx.x;
    if (idx < 2 * 2 * 4 * 32) g_cnt[idx] = 0u;
}

__global__ void k_zero() {
    int idx = blockIdx.x * blockDim.x + threadIdx.x;
    if (idx < 256 * BB * 2) g_stateA[idx] = 0.0f;
}

// ---------------------------------------------------------------------------
__global__ void k_table(const float* __restrict__ emb,
                        const float* __restrict__ w_in) {
    int v = blockIdx.x;
    int j = threadIdx.x * 4;
    const float* er = emb + v * EE;
    float4 acc = make_float4(0.f, 0.f, 0.f, 0.f);
#pragma unroll 4
    for (int e = 0; e < EE; ++e) {
        float ev = er[e];
        float4 wv = *reinterpret_cast<const float4*>(w_in + (size_t)e * (2 * HH) + j);
        acc.x = fmaf(ev, wv.x, acc.x);
        acc.y = fmaf(ev, wv.y, acc.y);
        acc.z = fmaf(ev, wv.z, acc.z);
        acc.w = fmaf(ev, wv.w, acc.w);
    }
    g_table_t[(j + 0) * VV + v] = acc.x;
    g_table_t[(j + 1) * VV + v] = acc.y;
    g_table_t[(j + 2) * VV + v] = acc.z;
    g_table_t[(j + 3) * VV + v] = acc.w;
}

// ---------------------------------------------------------------------------
// Persistent RHN pass. 128 CTAs = 2 rowgroups x 64 colgroups.
// CTA: 32 rows x 8 cols; 8 warps = 4 colpairs x 2 khalf (warp = 32 rows).
// Column-half pipelining: kp half h is produced only by CTAs with cg-half h
// and consumed only by khalf-h warps. Each khalf group independently:
// polls its (rg,half) spread counters -> stages its 32KB half -> dot.
// s_old kept in a register (same thread produced it) -> no cross-half read.
// khalf1 partials -> parity-double-buffered scratch -> khalf0 epilogue.
// ---------------------------------------------------------------------------
template <int PASS>
__global__ void __launch_bounds__(NTH, 1) k_rhn(
    const int*   __restrict__ x,
    const float* __restrict__ w_h,
    const float* __restrict__ b_h)
{
    extern __shared__ float smraw[];
    ulonglong2* w_pk    = reinterpret_cast<ulonglong2*>(smraw);          // [4][8][256] 131072 B
    float2*     s_pair  = reinterpret_cast<float2*>(smraw + 32768);      // [256][32]    65536 B
    float2*     scratch = reinterpret_cast<float2*>(smraw + 49152);      // [2][8][32]    4096 B

    const int tid   = threadIdx.x;
    const int cid   = blockIdx.x;
    const int rg    = cid >> 6;
    const int cg    = cid & 63;
    const int w     = tid >> 5;
    const int lane  = tid & 31;
    const int cpq   = w & 3;
    const int khalf = w >> 2;           // warps 0-3: lower kp half, 4-7: upper
    const int r     = lane;
    const int grow  = rg * 32 + r;
    const int j0    = cg * 8 + 2 * cpq;
    const int kpj   = cg * 4 + cpq;
    const int lt    = tid & 127;        // thread index within khalf group

    // ---- stage weights: w_pk[(d*8+cp)*256 + kp] = {(wh0,wh1),(wg0,wg1)} ----
    for (int idx = tid; idx < 4 * 8 * 256; idx += NTH) {
        int cp = idx & 7;
        int kp = (idx >> 3) & 255;
        int d  = idx >> 11;
        const float* b0 = w_h + (((size_t)(PASS * 4 + d) * HH + 2 * kp) * (2 * HH)) + cg * 8 + cp;
        const float* b1 = b0 + 2 * HH;
        w_pk[(d * 8 + cp) * 256 + kp] =
            make_ulonglong2(pk2(b0[0], b1[0]), pk2(b0[HH], b1[HH]));
    }

    float bh0[4], bg0[4], bh1[4], bg1[4];
#pragma unroll
    for (int d = 0; d < 4; ++d) {
        const float* bb = b_h + (size_t)(PASS * 4 + d) * (2 * HH);
        bh0[d] = bb[j0];      bg0[d] = bb[HH + j0];
        bh1[d] = bb[j0 + 1];  bg1[d] = bb[HH + j0 + 1];
    }
    __syncthreads();

    const float* s_cur = g_stateA;
    float*       s_nxt = g_stateB;
    const unsigned pbase = (unsigned)PASS * 2048u;

    // producer counter of THIS CTA: (rg, cg-half, cg&3)
    unsigned* my_cnt = (unsigned*)&g_cnt[(((rg * 2) + (cg >> 5)) * 4 + (cg & 3)) * 32];
    // consumer counters for this khalf group: (rg, khalf, 0..3)
    unsigned* grp_cnt = (unsigned*)&g_cnt[(((rg * 2) + khalf) * 4) * 32];

    const ull* sp = reinterpret_cast<const ull*>(s_pair) + khalf * 128 * 32 + r;

    float2 s_own = make_float2(0.f, 0.f);   // this thread's (kpj, grow) state pair

    // prefetch t=0 input (khalf0 consumes it)
    float4 inp_cur = make_float4(0.f, 0.f, 0.f, 0.f);
    if (khalf == 0) {
        if (PASS == 0) {
            int xv = x[0 * BB + grow];
            inp_cur = make_float4(g_table_t[(size_t)j0 * VV + xv],
                                  g_table_t[(size_t)(HH + j0) * VV + xv],
                                  g_table_t[(size_t)(j0 + 1) * VV + xv],
                                  g_table_t[(size_t)(HH + j0 + 1) * VV + xv]);
        } else {
            inp_cur = make_float4(__ldcg(&g_in1[0][j0 * BB + grow]),
                                  __ldcg(&g_in1[0][(HH + j0) * BB + grow]),
                                  __ldcg(&g_in1[0][(j0 + 1) * BB + grow]),
                                  __ldcg(&g_in1[0][(HH + j0 + 1) * BB + grow]));
        }
    }

    unsigned sidx = 0;
    for (int t = 0; t < TT; ++t) {
        float4 inp_next = make_float4(0.f, 0.f, 0.f, 0.f);
        for (int d = 0; d < 4; ++d) {
            // ---- group: poll my half's producers, then stage my 32KB half ----
            {
                unsigned tgt = 8u * (pbase + sidx);
                if (cpq == 0 && lane < 4) {
                    unsigned* cp_ = grp_cnt + lane * 32;
                    unsigned v;
                    do {
                        asm volatile("ld.acquire.gpu.global.u32 %0,[%1];"
                                     : "=r"(v) : "l"(cp_) : "memory");
                    } while (v < tgt);
                }
                asm volatile("bar.sync %0, 128;" :: "r"(2 + khalf) : "memory");
#pragma unroll
                for (int i2 = 0; i2 < 16; ++i2) {
                    int idx = lt + i2 * 128;            // 0..2047 within half
                    int kp = khalf * 128 + (idx >> 4);
                    int i  = idx & 15;
                    reinterpret_cast<float4*>(s_pair)[kp * 16 + i] =
                        __ldcg(reinterpret_cast<const float4*>(
                            s_cur + (size_t)kp * 128 + rg * 64) + i);
                }
                asm volatile("bar.sync %0, 128;" :: "r"(2 + khalf) : "memory");
            }

            // prefetch next-t input during compute
            if (d == 0 && khalf == 0 && t + 1 < TT) {
                if (PASS == 0) {
                    int xv = x[(t + 1) * BB + grow];
                    inp_next = make_float4(g_table_t[(size_t)j0 * VV + xv],
                                           g_table_t[(size_t)(HH + j0) * VV + xv],
                                           g_table_t[(size_t)(j0 + 1) * VV + xv],
                                           g_table_t[(size_t)(HH + j0 + 1) * VV + xv]);
                } else {
                    inp_next = make_float4(__ldcg(&g_in1[t + 1][j0 * BB + grow]),
                                           __ldcg(&g_in1[t + 1][(HH + j0) * BB + grow]),
                                           __ldcg(&g_in1[t + 1][(j0 + 1) * BB + grow]),
                                           __ldcg(&g_in1[t + 1][(HH + j0 + 1) * BB + grow]));
                }
            }

            // ---- packed k-pair dot over this khalf (128 kp), 2 cols ----
            ull ah0 = pk2(0.f, 0.f), ag0 = pk2(0.f, 0.f);
            ull ah1 = pk2(0.f, 0.f), ag1 = pk2(0.f, 0.f);
            const ulonglong2* wp0 = w_pk + (size_t)(d * 8 + 2 * cpq) * 256 + khalf * 128;
            const ulonglong2* wp1 = wp0 + 256;
#pragma unroll 8
            for (int q = 0; q < 128; ++q) {
                ull sv = sp[q * 32];                // (s_k0, s_k1) pre-packed
                ulonglong2 w0 = wp0[q];
                ulonglong2 w1 = wp1[q];
                ah0 = fma2(sv, w0.x, ah0);
                ag0 = fma2(sv, w0.y, ag0);
                ah1 = fma2(sv, w1.x, ah1);
                ag1 = fma2(sv, w1.y, ag1);
            }
            float2 h0p = upk2(ah0), g0p = upk2(ag0);
            float2 h1p = upk2(ah1), g1p = upk2(ag1);

            const int par = (int)(sidx & 1u);
            if (khalf == 1) {
                scratch[par * 256 + (cpq * 2 + 0) * 32 + r] =
                    make_float2(h0p.x + h0p.y, g0p.x + g0p.y);
                scratch[par * 256 + (cpq * 2 + 1) * 32 + r] =
                    make_float2(h1p.x + h1p.y, g1p.x + g1p.y);
            }
            __syncthreads();   // khalf1 partials visible; khalf1 runs ahead after

            if (khalf == 0) {
                float2 o0 = scratch[par * 256 + (cpq * 2 + 0) * 32 + r];
                float2 o1 = scratch[par * 256 + (cpq * 2 + 1) * 32 + r];
                float acc_h0 = bh0[d] + h0p.x + h0p.y + o0.x;
                float acc_g0 = bg0[d] + g0p.x + g0p.y + o0.y;
                float acc_h1 = bh1[d] + h1p.x + h1p.y + o1.x;
                float acc_g1 = bg1[d] + g1p.x + g1p.y + o1.y;
                if (d == 0) {
                    acc_h0 += inp_cur.x; acc_g0 += inp_cur.y;
                    acc_h1 += inp_cur.z; acc_g1 += inp_cur.w;
                }

                float gt0 = 1.0f / (1.0f + expf(-acc_g0));
                float gt1 = 1.0f / (1.0f + expf(-acc_g1));
                float ht0 = tanhf(acc_h0);
                float ht1 = tanhf(acc_h1);
                float sn0 = ht0 * gt0 + s_own.x * (1.0f - gt0);
                float sn1 = ht1 * gt1 + s_own.y * (1.0f - gt1);
                s_own = make_float2(sn0, sn1);

                __stcg(reinterpret_cast<float2*>(s_nxt) + kpj * BB + grow,
                       make_float2(sn0, sn1));
                if (d == 3) {
                    float* ob = (PASS == 0) ? g_out0[t] : g_out1[t];
                    ob[j0 * BB + grow]       = sn0;
                    ob[(j0 + 1) * BB + grow] = sn1;
                }
                __threadfence();
                asm volatile("bar.sync 1, 128;" ::: "memory");   // khalf0 group
                if (tid == 0) {
                    asm volatile("red.release.gpu.global.add.u32 [%0], 1;"
                                 :: "l"(my_cnt) : "memory");
                }
            }

            const float* tmp = s_nxt;
            s_nxt = (float*)s_cur;
            s_cur = tmp;
            ++sidx;
        }
        inp_cur = inp_next;
    }
}

// ---------------------------------------------------------------------------
// g_in1[t][j][b] = sum_h g_out0[t][h][b] * w_in[1][h][j]   (FFMA2)
// ---------------------------------------------------------------------------
__global__ void k_inp1(const float* __restrict__ w_in) {
    int bid = blockIdx.x;
    int t   = bid >> 4;
    int jb  = bid & 15;
    int tid = threadIdx.x;
    int b   = tid & 63;
    int js  = tid >> 6;
    int j0  = jb * 64 + js * 16;

    ull acc[8];
#pragma unroll
    for (int i = 0; i < 8; ++i) acc[i] = pk2(0.f, 0.f);

    const float* o  = g_out0[t];
    const float* w1 = w_in + (size_t)EE * (2 * HH);
#pragma unroll 2
    for (int h = 0; h < HH; ++h) {
        ull svp = pkd(o[h * BB + b]);
        const ulonglong2* wr = reinterpret_cast<const ulonglong2*>(w1 + (size_t)h * (2 * HH) + j0);
        ulonglong2 q0 = wr[0], q1 = wr[1], q2 = wr[2], q3 = wr[3];
        acc[0] = fma2(svp, q0.x, acc[0]);  acc[1] = fma2(svp, q0.y, acc[1]);
        acc[2] = fma2(svp, q1.x, acc[2]);  acc[3] = fma2(svp, q1.y, acc[3]);
        acc[4] = fma2(svp, q2.x, acc[4]);  acc[5] = fma2(svp, q2.y, acc[5]);
        acc[6] = fma2(svp, q3.x, acc[6]);  acc[7] = fma2(svp, q3.y, acc[7]);
    }
#pragma unroll
    for (int i = 0; i < 8; ++i) {
        float2 v = upk2(acc[i]);
        g_in1[t][(j0 + 2 * i) * BB + b]     = v.x;
        g_in1[t][(j0 + 2 * i + 1) * BB + b] = v.y;
    }
}

// ---------------------------------------------------------------------------
__global__ void k_logits(const float* __restrict__ w_fc,
                         const float* __restrict__ b_fc,
                         float* __restrict__ out) {
    int bid = blockIdx.x;
    int t   = bid >> 2;
    int vb  = bid & 3;
    int tid = threadIdx.x;
    int b   = tid & 63;
    int vs  = tid >> 6;
    int v0  = vb * 64 + vs * 16;

    ull acc[8];
    const ulonglong2* bp = reinterpret_cast<const ulonglong2*>(b_fc + v0);
#pragma unroll
    for (int i = 0; i < 4; ++i) {
        ulonglong2 bq = bp[i];
        acc[2 * i] = bq.x; acc[2 * i + 1] = bq.y;
    }

    const float* o = g_out1[t];
#pragma unroll 2
    for (int h = 0; h < HH; ++h) {
        ull svp = pkd(o[h * BB + b]);
        const ulonglong2* wr = reinterpret_cast<const ulonglong2*>(w_fc + (size_t)h * VV + v0);
        ulonglong2 q0 = wr[0], q1 = wr[1], q2 = wr[2], q3 = wr[3];
        acc[0] = fma2(svp, q0.x, acc[0]);  acc[1] = fma2(svp, q0.y, acc[1]);
        acc[2] = fma2(svp, q1.x, acc[2]);  acc[3] = fma2(svp, q1.y, acc[3]);
        acc[4] = fma2(svp, q2.x, acc[4]);  acc[5] = fma2(svp, q2.y, acc[5]);
        acc[6] = fma2(svp, q3.x, acc[6]);  acc[7] = fma2(svp, q3.y, acc[7]);
    }

    ull* dst = reinterpret_cast<ull*>(out + ((size_t)(t * BB + b)) * VV + v0);
#pragma unroll
    for (int i = 0; i < 8; ++i) dst[i] = acc[i];
}

// ---------------------------------------------------------------------------
// s_final[l][b][h] from g_stateA in [kp][b][2] layout
// ---------------------------------------------------------------------------
__global__ void k_sfinal(float* __restrict__ out, int l) {
    int idx = blockIdx.x * blockDim.x + threadIdx.x;
    if (idx >= BB * HH) return;
    int b = idx >> 9;
    int h = idx & 511;
    out[(size_t)TT * BB * VV + (size_t)l * BB * HH + idx] =
        g_stateA[(h >> 1) * 128 + b * 2 + (h & 1)];
}

// ---------------------------------------------------------------------------
extern "C" void kernel_launch(void* const* d_in, const int* in_sizes, int n_in,
                              void* d_out, int out_size) {
    const int*   x    = (const int*)  d_in[0];
    const float* emb  = (const float*)d_in[1];
    const float* w_in = (const float*)d_in[2];
    const float* w_h  = (const float*)d_in[3];
    const float* b_h  = (const float*)d_in[4];
    const float* w_fc = (const float*)d_in[5];
    const float* b_fc = (const float*)d_in[6];
    float* out = (float*)d_out;

    const int smem_bytes = 131072 + 65536 + 4096;   // 200704 B
    static bool attr_done = false;
    if (!attr_done) {
        cudaFuncSetAttribute(k_rhn<0>, cudaFuncAttributeMaxDynamicSharedMemorySize, smem_bytes);
        cudaFuncSetAttribute(k_rhn<1>, cudaFuncAttributeMaxDynamicSharedMemorySize, smem_bytes);
        attr_done = true;
    }

    const bool has_sfinal = (out_size >= TT * BB * VV + 2 * BB * HH);

    k_reset<<<2, 256>>>();                                              // 1
    k_table<<<VV, 256>>>(emb, w_in);                                    // 2
    k_zero<<<(256 * BB * 2 + 255) / 256, 256>>>();                      // 3
    k_rhn<0><<<GRID_REC, NTH, smem_bytes>>>(x, w_h, b_h);               // 4 <- profiled
    if (has_sfinal)
        k_sfinal<<<(BB * HH + 255) / 256, 256>>>(out, 0);
    k_inp1<<<TT * 16, 256>>>(w_in);
    k_zero<<<(256 * BB * 2 + 255) / 256, 256>>>();
    k_rhn<1><<<GRID_REC, NTH, smem_bytes>>>(x, w_h, b_h);
    k_logits<<<TT * 4, 256>>>(w_fc, b_fc, out);
    if (has_sfinal)
        k_sfinal<<<(BB * HH + 255) / 256, 256>>>(out, 1);
}

// round 13
// speedup vs baseline: 2.1115x; 1.0698x over previous
#include <cuda_runtime.h>
#include <math.h>

#define TT 512
#define BB 64
#define VV 256
#define EE 512
#define HH 512

#define GRID_REC 128
#define NTH 256

typedef unsigned long long ull;
__device__ __forceinline__ ull pk2(float x, float y) {
    ull r; asm("mov.b64 %0,{%1,%2};" : "=l"(r) : "f"(x), "f"(y)); return r;
}
__device__ __forceinline__ ull pkd(float x) {
    ull r; asm("mov.b64 %0,{%1,%1};" : "=l"(r) : "f"(x)); return r;
}
__device__ __forceinline__ ull fma2(ull a, ull b, ull c) {
    ull d; asm("fma.rn.f32x2 %0,%1,%2,%3;" : "=l"(d) : "l"(a), "l"(b), "l"(c)); return d;
}
__device__ __forceinline__ float2 upk2(ull a) {
    float2 r; asm("mov.b64 {%0,%1},%2;" : "=f"(r.x), "=f"(r.y) : "l"(a)); return r;
}

// ---------------------------------------------------------------------------
// Static scratch.  State layout: [kp][b][2]  (k-pair interleaved, kp=h>>1)
// ---------------------------------------------------------------------------
__device__ float g_table_t[2 * HH * VV];          // [j][v] : (emb @ w_in[0])^T
__device__ float g_stateA[256 * BB * 2];          // state ping [kp][b][2]
__device__ float g_stateB[256 * BB * 2];          // state pong [kp][b][2]
__device__ float g_out0[TT][HH * BB];             // layer-0 outputs [t][h][b]
__device__ float g_out1[TT][HH * BB];             // layer-1 outputs [t][h][b]
__device__ float g_in1[TT][2 * HH * BB];          // layer-1 input preact [t][j][b]
__device__ unsigned g_cnt[2 * 4 * 2 * 32];        // [rg][kquarter][sub] counters

__global__ void k_reset() {
    int idx = blockIdx.x * blockDim.x + threadIdx.x;
    if (idx < 2 * 4 * 2 * 32) g_cnt[idx] = 0u;
}

__global__ void k_zero() {
    int idx = blockIdx.x * blockDim.x + threadIdx.x;
    if (idx < 256 * BB * 2) g_stateA[idx] = 0.0f;
}

// ---------------------------------------------------------------------------
__global__ void k_table(const float* __restrict__ emb,
                        const float* __restrict__ w_in) {
    int v = blockIdx.x;
    int j = threadIdx.x * 4;
    const float* er = emb + v * EE;
    float4 acc = make_float4(0.f, 0.f, 0.f, 0.f);
#pragma unroll 4
    for (int e = 0; e < EE; ++e) {
        float ev = er[e];
        float4 wv = *reinterpret_cast<const float4*>(w_in + (size_t)e * (2 * HH) + j);
        acc.x = fmaf(ev, wv.x, acc.x);
        acc.y = fmaf(ev, wv.y, acc.y);
        acc.z = fmaf(ev, wv.z, acc.z);
        acc.w = fmaf(ev, wv.w, acc.w);
    }
    g_table_t[(j + 0) * VV + v] = acc.x;
    g_table_t[(j + 1) * VV + v] = acc.y;
    g_table_t[(j + 2) * VV + v] = acc.z;
    g_table_t[(j + 3) * VV + v] = acc.w;
}

// ---------------------------------------------------------------------------
// Persistent RHN pass. 128 CTAs = 2 rowgroups x 64 colgroups.
// CTA tile 32 rows x 8 h-cols. 8 warps = 2 rowhalves x 4 k-quarters.
// Thread = 2 rows x 2 cols x 64 kp: 8 FFMA2 accumulators (register tiling).
// Weights SMEM [d][kp][8 cols] -> the 8 cols of one kp share a 128B line:
// per kp per warp = 2 state LDS.64 + 2 weight LDS.128 = 4 wavefronts.
// k-quarter groups poll/stage independently; 3-way scratch reduce into kq0,
// which keeps s_old in registers, does epilogue, stores, signals.
// ---------------------------------------------------------------------------
template <int PASS>
__global__ void __launch_bounds__(NTH, 1) k_rhn(
    const int*   __restrict__ x,
    const float* __restrict__ w_h,
    const float* __restrict__ b_h)
{
    extern __shared__ float smraw[];
    ulonglong2* w_pk    = reinterpret_cast<ulonglong2*>(smraw);          // [4][256][8] 131072 B
    float2*     s_pair  = reinterpret_cast<float2*>(smraw + 32768);      // [256][32]    65536 B
    float2*     scratch = reinterpret_cast<float2*>(smraw + 49152);      // [2][3][8][32] 12288 B

    const int tid  = threadIdx.x;
    const int cid  = blockIdx.x;
    const int rg   = cid >> 6;
    const int cg   = cid & 63;
    const int wid  = tid >> 5;
    const int lane = tid & 31;
    const int rh   = wid & 1;           // rowhalf
    const int kq   = wid >> 1;          // k-quarter 0..3
    const int rp   = lane >> 2;         // row-pair 0..7
    const int cp   = lane & 3;          // colpair 0..3
    const int R0   = rh * 16 + rp * 2;  // local rows
    const int R1   = R0 + 1;
    const int grow0 = rg * 32 + R0;
    const int grow1 = grow0 + 1;
    const int j0   = cg * 8 + 2 * cp;   // global h-col (even)
    const int kpj  = cg * 4 + cp;       // state kp owned by this thread
    const int lt2  = rh * 32 + lane;    // 0..63 within quarter group
    const int qbase = kq * 64;

    // ---- stage weights: w_pk[(d*256+kp)*8 + c] = {(wh0,wh1),(wg0,wg1)} ----
    for (int idx = tid; idx < 4 * 256 * 8; idx += NTH) {
        int c  = idx & 7;
        int kp = (idx >> 3) & 255;
        int d  = idx >> 11;
        const float* b0 = w_h + (((size_t)(PASS * 4 + d) * HH + 2 * kp) * (2 * HH)) + cg * 8 + c;
        const float* b1 = b0 + 2 * HH;
        w_pk[(d * 256 + kp) * 8 + c] =
            make_ulonglong2(pk2(b0[0], b1[0]), pk2(b0[HH], b1[HH]));
    }

    float bh0[4], bg0[4], bh1[4], bg1[4];
#pragma unroll
    for (int d = 0; d < 4; ++d) {
        const float* bb = b_h + (size_t)(PASS * 4 + d) * (2 * HH);
        bh0[d] = bb[j0];      bg0[d] = bb[HH + j0];
        bh1[d] = bb[j0 + 1];  bg1[d] = bb[HH + j0 + 1];
    }
    __syncthreads();

    const float* s_cur = g_stateA;
    float*       s_nxt = g_stateB;
    const unsigned pbase = (unsigned)PASS * 2048u;

    // producer counter: (rg, quarter cg>>4, sub (cg>>3)&1); consumer: (rg, kq, 0..1)
    unsigned* my_cnt  = (unsigned*)&g_cnt[((rg * 4 + (cg >> 4)) * 2 + ((cg >> 3) & 1)) * 32];
    unsigned* grp_cnt = (unsigned*)&g_cnt[((rg * 4 + kq) * 2) * 32];

    const ull* sq = reinterpret_cast<const ull*>(s_pair);

    float2 s_own0 = make_float2(0.f, 0.f);   // (kpj, grow0) state pair
    float2 s_own1 = make_float2(0.f, 0.f);   // (kpj, grow1)

    // t=0 input prefetch (kq0 consumes): per row (h0,g0,h1,g1)
    float4 inpA_cur = make_float4(0.f, 0.f, 0.f, 0.f);
    float4 inpB_cur = make_float4(0.f, 0.f, 0.f, 0.f);
    if (kq == 0) {
        if (PASS == 0) {
            int xv0 = x[0 * BB + grow0], xv1 = x[0 * BB + grow1];
            inpA_cur = make_float4(g_table_t[(size_t)j0 * VV + xv0],
                                   g_table_t[(size_t)(HH + j0) * VV + xv0],
                                   g_table_t[(size_t)(j0 + 1) * VV + xv0],
                                   g_table_t[(size_t)(HH + j0 + 1) * VV + xv0]);
            inpB_cur = make_float4(g_table_t[(size_t)j0 * VV + xv1],
                                   g_table_t[(size_t)(HH + j0) * VV + xv1],
                                   g_table_t[(size_t)(j0 + 1) * VV + xv1],
                                   g_table_t[(size_t)(HH + j0 + 1) * VV + xv1]);
        } else {
            inpA_cur = make_float4(__ldcg(&g_in1[0][j0 * BB + grow0]),
                                   __ldcg(&g_in1[0][(HH + j0) * BB + grow0]),
                                   __ldcg(&g_in1[0][(j0 + 1) * BB + grow0]),
                                   __ldcg(&g_in1[0][(HH + j0 + 1) * BB + grow0]));
            inpB_cur = make_float4(__ldcg(&g_in1[0][j0 * BB + grow1]),
                                   __ldcg(&g_in1[0][(HH + j0) * BB + grow1]),
                                   __ldcg(&g_in1[0][(j0 + 1) * BB + grow1]),
                                   __ldcg(&g_in1[0][(HH + j0 + 1) * BB + grow1]));
        }
    }

    unsigned sidx = 0;
    for (int t = 0; t < TT; ++t) {
        float4 inpA_next = make_float4(0.f, 0.f, 0.f, 0.f);
        float4 inpB_next = make_float4(0.f, 0.f, 0.f, 0.f);
        for (int d = 0; d < 4; ++d) {
            // ---- quarter group: poll my producers, stage my 16KB quarter ----
            {
                unsigned tgt = 8u * (pbase + sidx);
                if (rh == 0 && lane < 2) {
                    unsigned* cp_ = grp_cnt + lane * 32;
                    unsigned v;
                    do {
                        asm volatile("ld.acquire.gpu.global.u32 %0,[%1];"
                                     : "=r"(v) : "l"(cp_) : "memory");
                    } while (v < tgt);
                }
                asm volatile("bar.sync %0, 64;" :: "r"(2 + kq) : "memory");
#pragma unroll
                for (int i2 = 0; i2 < 16; ++i2) {
                    int idx = lt2 + i2 * 64;            // 0..1023
                    int kp  = qbase + (idx >> 4);
                    int i   = idx & 15;
                    reinterpret_cast<float4*>(s_pair)[kp * 16 + i] =
                        __ldcg(reinterpret_cast<const float4*>(
                            s_cur + (size_t)kp * 128 + rg * 64) + i);
                }
                asm volatile("bar.sync %0, 64;" :: "r"(2 + kq) : "memory");
            }

            // prefetch next-t input during compute
            if (d == 0 && kq == 0 && t + 1 < TT) {
                if (PASS == 0) {
                    int xv0 = x[(t + 1) * BB + grow0], xv1 = x[(t + 1) * BB + grow1];
                    inpA_next = make_float4(g_table_t[(size_t)j0 * VV + xv0],
                                            g_table_t[(size_t)(HH + j0) * VV + xv0],
                                            g_table_t[(size_t)(j0 + 1) * VV + xv0],
                                            g_table_t[(size_t)(HH + j0 + 1) * VV + xv0]);
                    inpB_next = make_float4(g_table_t[(size_t)j0 * VV + xv1],
                                            g_table_t[(size_t)(HH + j0) * VV + xv1],
                                            g_table_t[(size_t)(j0 + 1) * VV + xv1],
                                            g_table_t[(size_t)(HH + j0 + 1) * VV + xv1]);
                } else {
                    inpA_next = make_float4(__ldcg(&g_in1[t + 1][j0 * BB + grow0]),
                                            __ldcg(&g_in1[t + 1][(HH + j0) * BB + grow0]),
                                            __ldcg(&g_in1[t + 1][(j0 + 1) * BB + grow0]),
                                            __ldcg(&g_in1[t + 1][(HH + j0 + 1) * BB + grow0]));
                    inpB_next = make_float4(__ldcg(&g_in1[t + 1][j0 * BB + grow1]),
                                            __ldcg(&g_in1[t + 1][(HH + j0) * BB + grow1]),
                                            __ldcg(&g_in1[t + 1][(j0 + 1) * BB + grow1]),
                                            __ldcg(&g_in1[t + 1][(HH + j0 + 1) * BB + grow1]));
                }
            }

            // ---- register-tiled dot: 2 rows x 2 cols x 64 kp ----
            ull aH0r0 = 0, aG0r0 = 0, aH1r0 = 0, aG1r0 = 0;
            ull aH0r1 = 0, aG0r1 = 0, aH1r1 = 0, aG1r1 = 0;
            const ulonglong2* wq = w_pk + (size_t)d * 2048;
#pragma unroll 8
            for (int qq = 0; qq < 64; ++qq) {
                int q = qbase + qq;
                ull sv0 = sq[q * 32 + R0];
                ull sv1 = sq[q * 32 + R1];
                ulonglong2 wA = wq[q * 8 + 2 * cp];
                ulonglong2 wB = wq[q * 8 + 2 * cp + 1];
                aH0r0 = fma2(sv0, wA.x, aH0r0);
                aG0r0 = fma2(sv0, wA.y, aG0r0);
                aH1r0 = fma2(sv0, wB.x, aH1r0);
                aG1r0 = fma2(sv0, wB.y, aG1r0);
                aH0r1 = fma2(sv1, wA.x, aH0r1);
                aG0r1 = fma2(sv1, wA.y, aG0r1);
                aH1r1 = fma2(sv1, wB.x, aH1r1);
                aG1r1 = fma2(sv1, wB.y, aG1r1);
            }
            float2 pH0r0 = upk2(aH0r0), pG0r0 = upk2(aG0r0);
            float2 pH1r0 = upk2(aH1r0), pG1r0 = upk2(aG1r0);
            float2 pH0r1 = upk2(aH0r1), pG0r1 = upk2(aG0r1);
            float2 pH1r1 = upk2(aH1r1), pG1r1 = upk2(aG1r1);

            const int par = (int)(sidx & 1u);
            if (kq != 0) {
                float2* sc = scratch + ((par * 3 + (kq - 1)) * 8) * 32;
                sc[(2 * cp) * 32 + R0]     = make_float2(pH0r0.x + pH0r0.y, pG0r0.x + pG0r0.y);
                sc[(2 * cp + 1) * 32 + R0] = make_float2(pH1r0.x + pH1r0.y, pG1r0.x + pG1r0.y);
                sc[(2 * cp) * 32 + R1]     = make_float2(pH0r1.x + pH0r1.y, pG0r1.x + pG0r1.y);
                sc[(2 * cp + 1) * 32 + R1] = make_float2(pH1r1.x + pH1r1.y, pG1r1.x + pG1r1.y);
            }
            __syncthreads();

            if (kq == 0) {
                float h0r0 = bh0[d] + pH0r0.x + pH0r0.y;
                float g0r0 = bg0[d] + pG0r0.x + pG0r0.y;
                float h1r0 = bh1[d] + pH1r0.x + pH1r0.y;
                float g1r0 = bg1[d] + pG1r0.x + pG1r0.y;
                float h0r1 = bh0[d] + pH0r1.x + pH0r1.y;
                float g0r1 = bg0[d] + pG0r1.x + pG0r1.y;
                float h1r1 = bh1[d] + pH1r1.x + pH1r1.y;
                float g1r1 = bg1[d] + pG1r1.x + pG1r1.y;
#pragma unroll
                for (int kk = 0; kk < 3; ++kk) {
                    const float2* sc = scratch + ((par * 3 + kk) * 8) * 32;
                    float2 a0 = sc[(2 * cp) * 32 + R0];
                    float2 a1 = sc[(2 * cp + 1) * 32 + R0];
                    float2 b0 = sc[(2 * cp) * 32 + R1];
                    float2 b1 = sc[(2 * cp + 1) * 32 + R1];
                    h0r0 += a0.x; g0r0 += a0.y; h1r0 += a1.x; g1r0 += a1.y;
                    h0r1 += b0.x; g0r1 += b0.y; h1r1 += b1.x; g1r1 += b1.y;
                }
                if (d == 0) {
                    h0r0 += inpA_cur.x; g0r0 += inpA_cur.y;
                    h1r0 += inpA_cur.z; g1r0 += inpA_cur.w;
                    h0r1 += inpB_cur.x; g0r1 += inpB_cur.y;
                    h1r1 += inpB_cur.z; g1r1 += inpB_cur.w;
                }

                float gt;
                gt = 1.0f / (1.0f + expf(-g0r0));
                float sn00 = tanhf(h0r0) * gt + s_own0.x * (1.0f - gt);
                gt = 1.0f / (1.0f + expf(-g1r0));
                float sn10 = tanhf(h1r0) * gt + s_own0.y * (1.0f - gt);
                gt = 1.0f / (1.0f + expf(-g0r1));
                float sn01 = tanhf(h0r1) * gt + s_own1.x * (1.0f - gt);
                gt = 1.0f / (1.0f + expf(-g1r1));
                float sn11 = tanhf(h1r1) * gt + s_own1.y * (1.0f - gt);
                s_own0 = make_float2(sn00, sn10);
                s_own1 = make_float2(sn01, sn11);

                __stcg(reinterpret_cast<float2*>(s_nxt) + kpj * BB + grow0,
                       make_float2(sn00, sn10));
                __stcg(reinterpret_cast<float2*>(s_nxt) + kpj * BB + grow1,
                       make_float2(sn01, sn11));
                if (d == 3) {
                    float* ob = (PASS == 0) ? g_out0[t] : g_out1[t];
                    ob[j0 * BB + grow0]       = sn00;
                    ob[(j0 + 1) * BB + grow0] = sn10;
                    ob[j0 * BB + grow1]       = sn01;
                    ob[(j0 + 1) * BB + grow1] = sn11;
                }
                __threadfence();
                asm volatile("bar.sync 1, 64;" ::: "memory");
                if (tid == 0) {
                    asm volatile("red.release.gpu.global.add.u32 [%0], 1;"
                                 :: "l"(my_cnt) : "memory");
                }
            }

            const float* tmp = s_nxt;
            s_nxt = (float*)s_cur;
            s_cur = tmp;
            ++sidx;
        }
        inpA_cur = inpA_next;
        inpB_cur = inpB_next;
    }
}

// ---------------------------------------------------------------------------
// g_in1[t][j][b] = sum_h g_out0[t][h][b] * w_in[1][h][j]   (FFMA2)
// ---------------------------------------------------------------------------
__global__ void k_inp1(const float* __restrict__ w_in) {
    int bid = blockIdx.x;
    int t   = bid >> 4;
    int jb  = bid & 15;
    int tid = threadIdx.x;
    int b   = tid & 63;
    int js  = tid >> 6;
    int j0  = jb * 64 + js * 16;

    ull acc[8];
#pragma unroll
    for (int i = 0; i < 8; ++i) acc[i] = pk2(0.f, 0.f);

    const float* o  = g_out0[t];
    const float* w1 = w_in + (size_t)EE * (2 * HH);
#pragma unroll 2
    for (int h = 0; h < HH; ++h) {
        ull svp = pkd(o[h * BB + b]);
        const ulonglong2* wr = reinterpret_cast<const ulonglong2*>(w1 + (size_t)h * (2 * HH) + j0);
        ulonglong2 q0 = wr[0], q1 = wr[1], q2 = wr[2], q3 = wr[3];
        acc[0] = fma2(svp, q0.x, acc[0]);  acc[1] = fma2(svp, q0.y, acc[1]);
        acc[2] = fma2(svp, q1.x, acc[2]);  acc[3] = fma2(svp, q1.y, acc[3]);
        acc[4] = fma2(svp, q2.x, acc[4]);  acc[5] = fma2(svp, q2.y, acc[5]);
        acc[6] = fma2(svp, q3.x, acc[6]);  acc[7] = fma2(svp, q3.y, acc[7]);
    }
#pragma unroll
    for (int i = 0; i < 8; ++i) {
        float2 v = upk2(acc[i]);
        g_in1[t][(j0 + 2 * i) * BB + b]     = v.x;
        g_in1[t][(j0 + 2 * i + 1) * BB + b] = v.y;
    }
}

// ---------------------------------------------------------------------------
__global__ void k_logits(const float* __restrict__ w_fc,
                         const float* __restrict__ b_fc,
                         float* __restrict__ out) {
    int bid = blockIdx.x;
    int t   = bid >> 2;
    int vb  = bid & 3;
    int tid = threadIdx.x;
    int b   = tid & 63;
    int vs  = tid >> 6;
    int v0  = vb * 64 + vs * 16;

    ull acc[8];
    const ulonglong2* bp = reinterpret_cast<const ulonglong2*>(b_fc + v0);
#pragma unroll
    for (int i = 0; i < 4; ++i) {
        ulonglong2 bq = bp[i];
        acc[2 * i] = bq.x; acc[2 * i + 1] = bq.y;
    }

    const float* o = g_out1[t];
#pragma unroll 2
    for (int h = 0; h < HH; ++h) {
        ull svp = pkd(o[h * BB + b]);
        const ulonglong2* wr = reinterpret_cast<const ulonglong2*>(w_fc + (size_t)h * VV + v0);
        ulonglong2 q0 = wr[0], q1 = wr[1], q2 = wr[2], q3 = wr[3];
        acc[0] = fma2(svp, q0.x, acc[0]);  acc[1] = fma2(svp, q0.y, acc[1]);
        acc[2] = fma2(svp, q1.x, acc[2]);  acc[3] = fma2(svp, q1.y, acc[3]);
        acc[4] = fma2(svp, q2.x, acc[4]);  acc[5] = fma2(svp, q2.y, acc[5]);
        acc[6] = fma2(svp, q3.x, acc[6]);  acc[7] = fma2(svp, q3.y, acc[7]);
    }

    ull* dst = reinterpret_cast<ull*>(out + ((size_t)(t * BB + b)) * VV + v0);
#pragma unroll
    for (int i = 0; i < 8; ++i) dst[i] = acc[i];
}

// ---------------------------------------------------------------------------
// s_final[l][b][h] from g_stateA in [kp][b][2] layout
// ---------------------------------------------------------------------------
__global__ void k_sfinal(float* __restrict__ out, int l) {
    int idx = blockIdx.x * blockDim.x + threadIdx.x;
    if (idx >= BB * HH) return;
    int b = idx >> 9;
    int h = idx & 511;
    out[(size_t)TT * BB * VV + (size_t)l * BB * HH + idx] =
        g_stateA[(h >> 1) * 128 + b * 2 + (h & 1)];
}

// ---------------------------------------------------------------------------
extern "C" void kernel_launch(void* const* d_in, const int* in_sizes, int n_in,
                              void* d_out, int out_size) {
    const int*   x    = (const int*)  d_in[0];
    const float* emb  = (const float*)d_in[1];
    const float* w_in = (const float*)d_in[2];
    const float* w_h  = (const float*)d_in[3];
    const float* b_h  = (const float*)d_in[4];
    const float* w_fc = (const float*)d_in[5];
    const float* b_fc = (const float*)d_in[6];
    float* out = (float*)d_out;

    const int smem_bytes = 131072 + 65536 + 12288;   // 208896 B
    static bool attr_done = false;
    if (!attr_done) {
        cudaFuncSetAttribute(k_rhn<0>, cudaFuncAttributeMaxDynamicSharedMemorySize, smem_bytes);
        cudaFuncSetAttribute(k_rhn<1>, cudaFuncAttributeMaxDynamicSharedMemorySize, smem_bytes);
        attr_done = true;
    }

    const bool has_sfinal = (out_size >= TT * BB * VV + 2 * BB * HH);

    k_reset<<<2, 256>>>();                                              // 1
    k_table<<<VV, 256>>>(emb, w_in);                                    // 2
    k_zero<<<(256 * BB * 2 + 255) / 256, 256>>>();                      // 3
    k_rhn<0><<<GRID_REC, NTH, smem_bytes>>>(x, w_h, b_h);               // 4 <- profiled
    if (has_sfinal)
        k_sfinal<<<(BB * HH + 255) / 256, 256>>>(out, 0);
    k_inp1<<<TT * 16, 256>>>(w_in);
    k_zero<<<(256 * BB * 2 + 255) / 256, 256>>>();
    k_rhn<1><<<GRID_REC, NTH, smem_bytes>>>(x, w_h, b_h);
    k_logits<<<TT * 4, 256>>>(w_fc, b_fc, out);
    if (has_sfinal)
        k_sfinal<<<(BB * HH + 255) / 256, 256>>>(out, 1);
}

// round 14
// speedup vs baseline: 2.2304x; 1.0563x over previous
#include <cuda_runtime.h>
#include <math.h>

#define TT 512
#define BB 64
#define VV 256
#define EE 512
#define HH 512

#define GRID_REC 128
#define NTH 512

typedef unsigned long long ull;
__device__ __forceinline__ ull pk2(float x, float y) {
    ull r; asm("mov.b64 %0,{%1,%2};" : "=l"(r) : "f"(x), "f"(y)); return r;
}
__device__ __forceinline__ ull pkd(float x) {
    ull r; asm("mov.b64 %0,{%1,%1};" : "=l"(r) : "f"(x)); return r;
}
__device__ __forceinline__ ull fma2(ull a, ull b, ull c) {
    ull d; asm("fma.rn.f32x2 %0,%1,%2,%3;" : "=l"(d) : "l"(a), "l"(b), "l"(c)); return d;
}
__device__ __forceinline__ float2 upk2(ull a) {
    float2 r; asm("mov.b64 {%0,%1},%2;" : "=f"(r.x), "=f"(r.y) : "l"(a)); return r;
}

// ---------------------------------------------------------------------------
// Static scratch.  State layout: [kp][b][2]  (k-pair interleaved, kp=h>>1)
// ---------------------------------------------------------------------------
__device__ float g_table_t[2 * HH * VV];          // [j][v] : (emb @ w_in[0])^T
__device__ float g_stateA[256 * BB * 2];          // state ping [kp][b][2]
__device__ float g_stateB[256 * BB * 2];          // state pong [kp][b][2]
__device__ float g_out0[TT][HH * BB];             // layer-0 outputs [t][h][b]
__device__ float g_out1[TT][HH * BB];             // layer-1 outputs [t][h][b]
__device__ float g_in1[TT][2 * HH * BB];          // layer-1 input preact [t][j][b]
__device__ unsigned g_cnt[2 * 8 * 32];            // [rg][keighth] counters

__global__ void k_reset() {
    int idx = blockIdx.x * blockDim.x + threadIdx.x;
    if (idx < 2 * 8 * 32) g_cnt[idx] = 0u;
}

__global__ void k_zero() {
    int idx = blockIdx.x * blockDim.x + threadIdx.x;
    if (idx < 256 * BB * 2) g_stateA[idx] = 0.0f;
}

// ---------------------------------------------------------------------------
__global__ void k_table(const float* __restrict__ emb,
                        const float* __restrict__ w_in) {
    int v = blockIdx.x;
    int j = threadIdx.x * 4;
    const float* er = emb + v * EE;
    float4 acc = make_float4(0.f, 0.f, 0.f, 0.f);
#pragma unroll 4
    for (int e = 0; e < EE; ++e) {
        float ev = er[e];
        float4 wv = *reinterpret_cast<const float4*>(w_in + (size_t)e * (2 * HH) + j);
        acc.x = fmaf(ev, wv.x, acc.x);
        acc.y = fmaf(ev, wv.y, acc.y);
        acc.z = fmaf(ev, wv.z, acc.z);
        acc.w = fmaf(ev, wv.w, acc.w);
    }
    g_table_t[(j + 0) * VV + v] = acc.x;
    g_table_t[(j + 1) * VV + v] = acc.y;
    g_table_t[(j + 2) * VV + v] = acc.z;
    g_table_t[(j + 3) * VV + v] = acc.w;
}

// ---------------------------------------------------------------------------
// Persistent RHN pass. 128 CTAs = 2 rowgroups x 64 colgroups.
// CTA tile 32 rows x 8 h-cols. 512 thr, 16 warps = 2 rowhalves x 8 k-eighths.
// Thread = 2 rows x 2 cols x 32 kp (8 FFMA2 accumulators).
// Each k-eighth group (64 thr) maps to ONE producer counter (8 CTAs):
// poll 1 counter -> stage its 8KB -> dot -> scratch partials.
// ke0 group: 7-way reduce + epilogue + store + signal (s_old in registers).
// Leader-release: bar.sync + red.release.gpu (no explicit threadfence).
// ---------------------------------------------------------------------------
template <int PASS>
__global__ void __launch_bounds__(NTH, 1) k_rhn(
    const int*   __restrict__ x,
    const float* __restrict__ w_h,
    const float* __restrict__ b_h)
{
    extern __shared__ float smraw[];
    ulonglong2* w_pk    = reinterpret_cast<ulonglong2*>(smraw);          // [4][256][8] 131072 B
    float2*     s_pair  = reinterpret_cast<float2*>(smraw + 32768);      // [256][32]    65536 B
    float2*     scratch = reinterpret_cast<float2*>(smraw + 49152);      // [2][7][8][33] 29568 B

    const int tid  = threadIdx.x;
    const int cid  = blockIdx.x;
    const int rg   = cid >> 6;
    const int cg   = cid & 63;
    const int wid  = tid >> 5;
    const int lane = tid & 31;
    const int rh   = wid >> 3;          // rowhalf
    const int ke   = wid & 7;           // k-eighth 0..7
    const int rp   = lane >> 2;         // row-pair 0..7
    const int cp   = lane & 3;          // colpair 0..3
    const int R0   = rh * 16 + rp * 2;
    const int R1   = R0 + 1;
    const int grow0 = rg * 32 + R0;
    const int grow1 = grow0 + 1;
    const int j0   = cg * 8 + 2 * cp;
    const int kpj  = cg * 4 + cp;
    const int lt   = rh * 32 + lane;    // 0..63 within ke group
    const int qbase = ke * 32;

    // ---- stage weights: w_pk[(d*256+kp)*8 + c] = {(wh0,wh1),(wg0,wg1)} ----
    for (int idx = tid; idx < 4 * 256 * 8; idx += NTH) {
        int c  = idx & 7;
        int kp = (idx >> 3) & 255;
        int d  = idx >> 11;
        const float* b0 = w_h + (((size_t)(PASS * 4 + d) * HH + 2 * kp) * (2 * HH)) + cg * 8 + c;
        const float* b1 = b0 + 2 * HH;
        w_pk[(d * 256 + kp) * 8 + c] =
            make_ulonglong2(pk2(b0[0], b1[0]), pk2(b0[HH], b1[HH]));
    }

    float bh0[4], bg0[4], bh1[4], bg1[4];
#pragma unroll
    for (int d = 0; d < 4; ++d) {
        const float* bb = b_h + (size_t)(PASS * 4 + d) * (2 * HH);
        bh0[d] = bb[j0];      bg0[d] = bb[HH + j0];
        bh1[d] = bb[j0 + 1];  bg1[d] = bb[HH + j0 + 1];
    }
    __syncthreads();

    const float* s_cur = g_stateA;
    float*       s_nxt = g_stateB;
    const unsigned pbase = (unsigned)PASS * 2048u;

    // producer: counter (rg, cg>>3). consumer group ke: counter (rg, ke).
    unsigned* my_cnt  = (unsigned*)&g_cnt[(rg * 8 + (cg >> 3)) * 32];
    unsigned* grp_cnt = (unsigned*)&g_cnt[(rg * 8 + ke) * 32];

    const ull* sq = reinterpret_cast<const ull*>(s_pair);

    float2 s_own0 = make_float2(0.f, 0.f);
    float2 s_own1 = make_float2(0.f, 0.f);

    // t=0 input prefetch (ke0 consumes)
    float4 inpA_cur = make_float4(0.f, 0.f, 0.f, 0.f);
    float4 inpB_cur = make_float4(0.f, 0.f, 0.f, 0.f);
    if (ke == 0) {
        if (PASS == 0) {
            int xv0 = x[0 * BB + grow0], xv1 = x[0 * BB + grow1];
            inpA_cur = make_float4(g_table_t[(size_t)j0 * VV + xv0],
                                   g_table_t[(size_t)(HH + j0) * VV + xv0],
                                   g_table_t[(size_t)(j0 + 1) * VV + xv0],
                                   g_table_t[(size_t)(HH + j0 + 1) * VV + xv0]);
            inpB_cur = make_float4(g_table_t[(size_t)j0 * VV + xv1],
                                   g_table_t[(size_t)(HH + j0) * VV + xv1],
                                   g_table_t[(size_t)(j0 + 1) * VV + xv1],
                                   g_table_t[(size_t)(HH + j0 + 1) * VV + xv1]);
        } else {
            inpA_cur = make_float4(__ldcg(&g_in1[0][j0 * BB + grow0]),
                                   __ldcg(&g_in1[0][(HH + j0) * BB + grow0]),
                                   __ldcg(&g_in1[0][(j0 + 1) * BB + grow0]),
                                   __ldcg(&g_in1[0][(HH + j0 + 1) * BB + grow0]));
            inpB_cur = make_float4(__ldcg(&g_in1[0][j0 * BB + grow1]),
                                   __ldcg(&g_in1[0][(HH + j0) * BB + grow1]),
                                   __ldcg(&g_in1[0][(j0 + 1) * BB + grow1]),
                                   __ldcg(&g_in1[0][(HH + j0 + 1) * BB + grow1]));
        }
    }

    unsigned sidx = 0;
    for (int t = 0; t < TT; ++t) {
        float4 inpA_next = make_float4(0.f, 0.f, 0.f, 0.f);
        float4 inpB_next = make_float4(0.f, 0.f, 0.f, 0.f);
        for (int d = 0; d < 4; ++d) {
            // ---- ke group: poll its single producer counter, stage 8KB ----
            {
                unsigned tgt = 8u * (pbase + sidx);
                if (lt == 0) {
                    unsigned v;
                    do {
                        asm volatile("ld.acquire.gpu.global.u32 %0,[%1];"
                                     : "=r"(v) : "l"(grp_cnt) : "memory");
                    } while (v < tgt);
                }
                asm volatile("bar.sync %0, 64;" :: "r"(2 + ke) : "memory");
#pragma unroll
                for (int i2 = 0; i2 < 8; ++i2) {
                    int idx = lt + i2 * 64;             // 0..511
                    int kp  = qbase + (idx >> 4);
                    int i   = idx & 15;
                    reinterpret_cast<float4*>(s_pair)[kp * 16 + i] =
                        __ldcg(reinterpret_cast<const float4*>(
                            s_cur + (size_t)kp * 128 + rg * 64) + i);
                }
                asm volatile("bar.sync %0, 64;" :: "r"(2 + ke) : "memory");
            }

            // prefetch next-t input during compute
            if (d == 0 && ke == 0 && t + 1 < TT) {
                if (PASS == 0) {
                    int xv0 = x[(t + 1) * BB + grow0], xv1 = x[(t + 1) * BB + grow1];
                    inpA_next = make_float4(g_table_t[(size_t)j0 * VV + xv0],
                                            g_table_t[(size_t)(HH + j0) * VV + xv0],
                                            g_table_t[(size_t)(j0 + 1) * VV + xv0],
                                            g_table_t[(size_t)(HH + j0 + 1) * VV + xv0]);
                    inpB_next = make_float4(g_table_t[(size_t)j0 * VV + xv1],
                                            g_table_t[(size_t)(HH + j0) * VV + xv1],
                                            g_table_t[(size_t)(j0 + 1) * VV + xv1],
                                            g_table_t[(size_t)(HH + j0 + 1) * VV + xv1]);
                } else {
                    inpA_next = make_float4(__ldcg(&g_in1[t + 1][j0 * BB + grow0]),
                                            __ldcg(&g_in1[t + 1][(HH + j0) * BB + grow0]),
                                            __ldcg(&g_in1[t + 1][(j0 + 1) * BB + grow0]),
                                            __ldcg(&g_in1[t + 1][(HH + j0 + 1) * BB + grow0]));
                    inpB_next = make_float4(__ldcg(&g_in1[t + 1][j0 * BB + grow1]),
                                            __ldcg(&g_in1[t + 1][(HH + j0) * BB + grow1]),
                                            __ldcg(&g_in1[t + 1][(j0 + 1) * BB + grow1]),
                                            __ldcg(&g_in1[t + 1][(HH + j0 + 1) * BB + grow1]));
                }
            }

            // ---- register-tiled dot: 2 rows x 2 cols x 32 kp ----
            ull aH0r0 = 0, aG0r0 = 0, aH1r0 = 0, aG1r0 = 0;
            ull aH0r1 = 0, aG0r1 = 0, aH1r1 = 0, aG1r1 = 0;
            const ulonglong2* wq = w_pk + (size_t)d * 2048;
#pragma unroll
            for (int qq = 0; qq < 32; ++qq) {
                int q = qbase + qq;
                ull sv0 = sq[q * 32 + R0];
                ull sv1 = sq[q * 32 + R1];
                ulonglong2 wA = wq[q * 8 + 2 * cp];
                ulonglong2 wB = wq[q * 8 + 2 * cp + 1];
                aH0r0 = fma2(sv0, wA.x, aH0r0);
                aG0r0 = fma2(sv0, wA.y, aG0r0);
                aH1r0 = fma2(sv0, wB.x, aH1r0);
                aG1r0 = fma2(sv0, wB.y, aG1r0);
                aH0r1 = fma2(sv1, wA.x, aH0r1);
                aG0r1 = fma2(sv1, wA.y, aG0r1);
                aH1r1 = fma2(sv1, wB.x, aH1r1);
                aG1r1 = fma2(sv1, wB.y, aG1r1);
            }
            float2 pH0r0 = upk2(aH0r0), pG0r0 = upk2(aG0r0);
            float2 pH1r0 = upk2(aH1r0), pG1r0 = upk2(aG1r0);
            float2 pH0r1 = upk2(aH0r1), pG0r1 = upk2(aG0r1);
            float2 pH1r1 = upk2(aH1r1), pG1r1 = upk2(aG1r1);

            const int par = (int)(sidx & 1u);
            if (ke != 0) {
                float2* sc = scratch + (par * 7 + (ke - 1)) * 264;
                sc[(2 * cp) * 33 + R0]     = make_float2(pH0r0.x + pH0r0.y, pG0r0.x + pG0r0.y);
                sc[(2 * cp + 1) * 33 + R0] = make_float2(pH1r0.x + pH1r0.y, pG1r0.x + pG1r0.y);
                sc[(2 * cp) * 33 + R1]     = make_float2(pH0r1.x + pH0r1.y, pG0r1.x + pG0r1.y);
                sc[(2 * cp + 1) * 33 + R1] = make_float2(pH1r1.x + pH1r1.y, pG1r1.x + pG1r1.y);
            }
            __syncthreads();

            if (ke == 0) {
                float h0r0 = bh0[d] + pH0r0.x + pH0r0.y;
                float g0r0 = bg0[d] + pG0r0.x + pG0r0.y;
                float h1r0 = bh1[d] + pH1r0.x + pH1r0.y;
                float g1r0 = bg1[d] + pG1r0.x + pG1r0.y;
                float h0r1 = bh0[d] + pH0r1.x + pH0r1.y;
                float g0r1 = bg0[d] + pG0r1.x + pG0r1.y;
                float h1r1 = bh1[d] + pH1r1.x + pH1r1.y;
                float g1r1 = bg1[d] + pG1r1.x + pG1r1.y;
#pragma unroll
                for (int kk = 0; kk < 7; ++kk) {
                    const float2* sc = scratch + (par * 7 + kk) * 264;
                    float2 a0 = sc[(2 * cp) * 33 + R0];
                    float2 a1 = sc[(2 * cp + 1) * 33 + R0];
                    float2 b0 = sc[(2 * cp) * 33 + R1];
                    float2 b1 = sc[(2 * cp + 1) * 33 + R1];
                    h0r0 += a0.x; g0r0 += a0.y; h1r0 += a1.x; g1r0 += a1.y;
                    h0r1 += b0.x; g0r1 += b0.y; h1r1 += b1.x; g1r1 += b1.y;
                }
                if (d == 0) {
                    h0r0 += inpA_cur.x; g0r0 += inpA_cur.y;
                    h1r0 += inpA_cur.z; g1r0 += inpA_cur.w;
                    h0r1 += inpB_cur.x; g0r1 += inpB_cur.y;
                    h1r1 += inpB_cur.z; g1r1 += inpB_cur.w;
                }

                float gt;
                gt = 1.0f / (1.0f + expf(-g0r0));
                float sn00 = tanhf(h0r0) * gt + s_own0.x * (1.0f - gt);
                gt = 1.0f / (1.0f + expf(-g1r0));
                float sn10 = tanhf(h1r0) * gt + s_own0.y * (1.0f - gt);
                gt = 1.0f / (1.0f + expf(-g0r1));
                float sn01 = tanhf(h0r1) * gt + s_own1.x * (1.0f - gt);
                gt = 1.0f / (1.0f + expf(-g1r1));
                float sn11 = tanhf(h1r1) * gt + s_own1.y * (1.0f - gt);
                s_own0 = make_float2(sn00, sn10);
                s_own1 = make_float2(sn01, sn11);

                __stcg(reinterpret_cast<float2*>(s_nxt) + kpj * BB + grow0,
                       make_float2(sn00, sn10));
                __stcg(reinterpret_cast<float2*>(s_nxt) + kpj * BB + grow1,
                       make_float2(sn01, sn11));
                if (d == 3) {
                    float* ob = (PASS == 0) ? g_out0[t] : g_out1[t];
                    ob[j0 * BB + grow0]       = sn00;
                    ob[(j0 + 1) * BB + grow0] = sn10;
                    ob[j0 * BB + grow1]       = sn01;
                    ob[(j0 + 1) * BB + grow1] = sn11;
                }
                // leader-release: bar orders the group's stores before tid0's red
                asm volatile("bar.sync 10, 64;" ::: "memory");
                if (tid == 0) {
                    asm volatile("red.release.gpu.global.add.u32 [%0], 1;"
                                 :: "l"(my_cnt) : "memory");
                }
            }

            const float* tmp = s_nxt;
            s_nxt = (float*)s_cur;
            s_cur = tmp;
            ++sidx;
        }
        inpA_cur = inpA_next;
        inpB_cur = inpB_next;
    }
}

// ---------------------------------------------------------------------------
// g_in1[t][j][b] = sum_h g_out0[t][h][b] * w_in[1][h][j]   (FFMA2)
// ---------------------------------------------------------------------------
__global__ void k_inp1(const float* __restrict__ w_in) {
    int bid = blockIdx.x;
    int t   = bid >> 4;
    int jb  = bid & 15;
    int tid = threadIdx.x;
    int b   = tid & 63;
    int js  = tid >> 6;
    int j0  = jb * 64 + js * 16;

    ull acc[8];
#pragma unroll
    for (int i = 0; i < 8; ++i) acc[i] = pk2(0.f, 0.f);

    const float* o  = g_out0[t];
    const float* w1 = w_in + (size_t)EE * (2 * HH);
#pragma unroll 2
    for (int h = 0; h < HH; ++h) {
        ull svp = pkd(o[h * BB + b]);
        const ulonglong2* wr = reinterpret_cast<const ulonglong2*>(w1 + (size_t)h * (2 * HH) + j0);
        ulonglong2 q0 = wr[0], q1 = wr[1], q2 = wr[2], q3 = wr[3];
        acc[0] = fma2(svp, q0.x, acc[0]);  acc[1] = fma2(svp, q0.y, acc[1]);
        acc[2] = fma2(svp, q1.x, acc[2]);  acc[3] = fma2(svp, q1.y, acc[3]);
        acc[4] = fma2(svp, q2.x, acc[4]);  acc[5] = fma2(svp, q2.y, acc[5]);
        acc[6] = fma2(svp, q3.x, acc[6]);  acc[7] = fma2(svp, q3.y, acc[7]);
    }
#pragma unroll
    for (int i = 0; i < 8; ++i) {
        float2 v = upk2(acc[i]);
        g_in1[t][(j0 + 2 * i) * BB + b]     = v.x;
        g_in1[t][(j0 + 2 * i + 1) * BB + b] = v.y;
    }
}

// ---------------------------------------------------------------------------
__global__ void k_logits(const float* __restrict__ w_fc,
                         const float* __restrict__ b_fc,
                         float* __restrict__ out) {
    int bid = blockIdx.x;
    int t   = bid >> 2;
    int vb  = bid & 3;
    int tid = threadIdx.x;
    int b   = tid & 63;
    int vs  = tid >> 6;
    int v0  = vb * 64 + vs * 16;

    ull acc[8];
    const ulonglong2* bp = reinterpret_cast<const ulonglong2*>(b_fc + v0);
#pragma unroll
    for (int i = 0; i < 4; ++i) {
        ulonglong2 bq = bp[i];
        acc[2 * i] = bq.x; acc[2 * i + 1] = bq.y;
    }

    const float* o = g_out1[t];
#pragma unroll 2
    for (int h = 0; h < HH; ++h) {
        ull svp = pkd(o[h * BB + b]);
        const ulonglong2* wr = reinterpret_cast<const ulonglong2*>(w_fc + (size_t)h * VV + v0);
        ulonglong2 q0 = wr[0], q1 = wr[1], q2 = wr[2], q3 = wr[3];
        acc[0] = fma2(svp, q0.x, acc[0]);  acc[1] = fma2(svp, q0.y, acc[1]);
        acc[2] = fma2(svp, q1.x, acc[2]);  acc[3] = fma2(svp, q1.y, acc[3]);
        acc[4] = fma2(svp, q2.x, acc[4]);  acc[5] = fma2(svp, q2.y, acc[5]);
        acc[6] = fma2(svp, q3.x, acc[6]);  acc[7] = fma2(svp, q3.y, acc[7]);
    }

    ull* dst = reinterpret_cast<ull*>(out + ((size_t)(t * BB + b)) * VV + v0);
#pragma unroll
    for (int i = 0; i < 8; ++i) dst[i] = acc[i];
}

// ---------------------------------------------------------------------------
// s_final[l][b][h] from g_stateA in [kp][b][2] layout
// ---------------------------------------------------------------------------
__global__ void k_sfinal(float* __restrict__ out, int l) {
    int idx = blockIdx.x * blockDim.x + threadIdx.x;
    if (idx >= BB * HH) return;
    int b = idx >> 9;
    int h = idx & 511;
    out[(size_t)TT * BB * VV + (size_t)l * BB * HH + idx] =
        g_stateA[(h >> 1) * 128 + b * 2 + (h & 1)];
}

// ---------------------------------------------------------------------------
extern "C" void kernel_launch(void* const* d_in, const int* in_sizes, int n_in,
                              void* d_out, int out_size) {
    const int*   x    = (const int*)  d_in[0];
    const float* emb  = (const float*)d_in[1];
    const float* w_in = (const float*)d_in[2];
    const float* w_h  = (const float*)d_in[3];
    const float* b_h  = (const float*)d_in[4];
    const float* w_fc = (const float*)d_in[5];
    const float* b_fc = (const float*)d_in[6];
    float* out = (float*)d_out;

    const int smem_bytes = 131072 + 65536 + 29568;   // 226176 B
    static bool attr_done = false;
    if (!attr_done) {
        cudaFuncSetAttribute(k_rhn<0>, cudaFuncAttributeMaxDynamicSharedMemorySize, smem_bytes);
        cudaFuncSetAttribute(k_rhn<1>, cudaFuncAttributeMaxDynamicSharedMemorySize, smem_bytes);
        attr_done = true;
    }

    const bool has_sfinal = (out_size >= TT * BB * VV + 2 * BB * HH);

    k_reset<<<2, 256>>>();                                              // 1
    k_table<<<VV, 256>>>(emb, w_in);                                    // 2
    k_zero<<<(256 * BB * 2 + 255) / 256, 256>>>();                      // 3
    k_rhn<0><<<GRID_REC, NTH, smem_bytes>>>(x, w_h, b_h);               // 4 <- profiled
    if (has_sfinal)
        k_sfinal<<<(BB * HH + 255) / 256, 256>>>(out, 0);
    k_inp1<<<TT * 16, 256>>>(w_in);
    k_zero<<<(256 * BB * 2 + 255) / 256, 256>>>();
    k_rhn<1><<<GRID_REC, NTH, smem_bytes>>>(x, w_h, b_h);
    k_logits<<<TT * 4, 256>>>(w_fc, b_fc, out);
    if (has_sfinal)
        k_sfinal<<<(BB * HH + 255) / 256, 256>>>(out, 1);
}

// round 15
// speedup vs baseline: 2.2407x; 1.0046x over previous
#include <cuda_runtime.h>
#include <math.h>

#define TT 512
#define BB 64
#define VV 256
#define EE 512
#define HH 512

#define GRID_REC 128
#define NTH 512

typedef unsigned long long ull;
__device__ __forceinline__ ull pk2(float x, float y) {
    ull r; asm("mov.b64 %0,{%1,%2};" : "=l"(r) : "f"(x), "f"(y)); return r;
}
__device__ __forceinline__ ull pkd(float x) {
    ull r; asm("mov.b64 %0,{%1,%1};" : "=l"(r) : "f"(x)); return r;
}
__device__ __forceinline__ ull fma2(ull a, ull b, ull c) {
    ull d; asm("fma.rn.f32x2 %0,%1,%2,%3;" : "=l"(d) : "l"(a), "l"(b), "l"(c)); return d;
}
__device__ __forceinline__ float2 upk2(ull a) {
    float2 r; asm("mov.b64 {%0,%1},%2;" : "=f"(r.x), "=f"(r.y) : "l"(a)); return r;
}

// ---------------------------------------------------------------------------
// Static scratch.  State layout: [kp][b][2]  (k-pair interleaved, kp=h>>1)
// ---------------------------------------------------------------------------
__device__ float g_table_t[2 * HH * VV];          // [j][v] : (emb @ w_in[0])^T
__device__ float g_stateA[256 * BB * 2];          // state ping [kp][b][2]
__device__ float g_stateB[256 * BB * 2];          // state pong [kp][b][2]
__device__ float g_out0[TT][HH * BB];             // layer-0 outputs [t][h][b]
__device__ float g_out1[TT][HH * BB];             // layer-1 outputs [t][h][b]
__device__ float g_in1[TT][2 * HH * BB];          // layer-1 input preact [t][j][b]
__device__ unsigned g_cnt[2 * 8 * 32];            // [rg][keighth] counters

__global__ void k_reset() {
    int idx = blockIdx.x * blockDim.x + threadIdx.x;
    if (idx < 2 * 8 * 32) g_cnt[idx] = 0u;
}

__global__ void k_zero() {
    int idx = blockIdx.x * blockDim.x + threadIdx.x;
    if (idx < 256 * BB * 2) g_stateA[idx] = 0.0f;
}

// ---------------------------------------------------------------------------
__global__ void k_table(const float* __restrict__ emb,
                        const float* __restrict__ w_in) {
    int v = blockIdx.x;
    int j = threadIdx.x * 4;
    const float* er = emb + v * EE;
    float4 acc = make_float4(0.f, 0.f, 0.f, 0.f);
#pragma unroll 4
    for (int e = 0; e < EE; ++e) {
        float ev = er[e];
        float4 wv = *reinterpret_cast<const float4*>(w_in + (size_t)e * (2 * HH) + j);
        acc.x = fmaf(ev, wv.x, acc.x);
        acc.y = fmaf(ev, wv.y, acc.y);
        acc.z = fmaf(ev, wv.z, acc.z);
        acc.w = fmaf(ev, wv.w, acc.w);
    }
    g_table_t[(j + 0) * VV + v] = acc.x;
    g_table_t[(j + 1) * VV + v] = acc.y;
    g_table_t[(j + 2) * VV + v] = acc.z;
    g_table_t[(j + 3) * VV + v] = acc.w;
}

// ---------------------------------------------------------------------------
// Persistent RHN pass. 128 CTAs = 2 rowgroups x 64 colgroups.
// CTA tile 32 rows x 8 h-cols. 512 thr, 16 warps = 2 rowhalves x 8 k-eighths.
// Thread = 2 rows x 2 cols x 32 kp (8 FFMA2 accumulators).
// Producer/consumer decoupling: groups ke=1..7 write scratch partials then
// bar.arrive(11,512) and roll straight into the next step's poll+stage+dot.
// ke0 group bar.sync(11,512), reduces, epilogue, stores, signals.
// Safety: group lead bounded to +1 step vs slowest ke0 (counter gating), so
// 2-deep parity scratch cannot be overwritten before consumption.
// ---------------------------------------------------------------------------
template <int PASS>
__global__ void __launch_bounds__(NTH, 1) k_rhn(
    const int*   __restrict__ x,
    const float* __restrict__ w_h,
    const float* __restrict__ b_h)
{
    extern __shared__ float smraw[];
    ulonglong2* w_pk    = reinterpret_cast<ulonglong2*>(smraw);          // [4][256][8] 131072 B
    float2*     s_pair  = reinterpret_cast<float2*>(smraw + 32768);      // [256][32]    65536 B
    float2*     scratch = reinterpret_cast<float2*>(smraw + 49152);      // [2][7][8][33] 29568 B

    const int tid  = threadIdx.x;
    const int cid  = blockIdx.x;
    const int rg   = cid >> 6;
    const int cg   = cid & 63;
    const int wid  = tid >> 5;
    const int lane = tid & 31;
    const int rh   = wid >> 3;          // rowhalf
    const int ke   = wid & 7;           // k-eighth 0..7
    const int rp   = lane >> 2;         // row-pair 0..7
    const int cp   = lane & 3;          // colpair 0..3
    const int R0   = rh * 16 + rp * 2;
    const int R1   = R0 + 1;
    const int grow0 = rg * 32 + R0;
    const int grow1 = grow0 + 1;
    const int j0   = cg * 8 + 2 * cp;
    const int kpj  = cg * 4 + cp;
    const int lt   = rh * 32 + lane;    // 0..63 within ke group
    const int qbase = ke * 32;

    // ---- stage weights: w_pk[(d*256+kp)*8 + c] = {(wh0,wh1),(wg0,wg1)} ----
    for (int idx = tid; idx < 4 * 256 * 8; idx += NTH) {
        int c  = idx & 7;
        int kp = (idx >> 3) & 255;
        int d  = idx >> 11;
        const float* b0 = w_h + (((size_t)(PASS * 4 + d) * HH + 2 * kp) * (2 * HH)) + cg * 8 + c;
        const float* b1 = b0 + 2 * HH;
        w_pk[(d * 256 + kp) * 8 + c] =
            make_ulonglong2(pk2(b0[0], b1[0]), pk2(b0[HH], b1[HH]));
    }

    float bh0[4], bg0[4], bh1[4], bg1[4];
#pragma unroll
    for (int d = 0; d < 4; ++d) {
        const float* bb = b_h + (size_t)(PASS * 4 + d) * (2 * HH);
        bh0[d] = bb[j0];      bg0[d] = bb[HH + j0];
        bh1[d] = bb[j0 + 1];  bg1[d] = bb[HH + j0 + 1];
    }
    __syncthreads();

    const float* s_cur = g_stateA;
    float*       s_nxt = g_stateB;
    const unsigned pbase = (unsigned)PASS * 2048u;

    // producer: counter (rg, cg>>3). consumer group ke: counter (rg, ke).
    unsigned* my_cnt  = (unsigned*)&g_cnt[(rg * 8 + (cg >> 3)) * 32];
    unsigned* grp_cnt = (unsigned*)&g_cnt[(rg * 8 + ke) * 32];

    const ull* sq = reinterpret_cast<const ull*>(s_pair);

    float2 s_own0 = make_float2(0.f, 0.f);
    float2 s_own1 = make_float2(0.f, 0.f);

    // t=0 input prefetch (ke0 consumes)
    float4 inpA_cur = make_float4(0.f, 0.f, 0.f, 0.f);
    float4 inpB_cur = make_float4(0.f, 0.f, 0.f, 0.f);
    if (ke == 0) {
        if (PASS == 0) {
            int xv0 = x[0 * BB + grow0], xv1 = x[0 * BB + grow1];
            inpA_cur = make_float4(g_table_t[(size_t)j0 * VV + xv0],
                                   g_table_t[(size_t)(HH + j0) * VV + xv0],
                                   g_table_t[(size_t)(j0 + 1) * VV + xv0],
                                   g_table_t[(size_t)(HH + j0 + 1) * VV + xv0]);
            inpB_cur = make_float4(g_table_t[(size_t)j0 * VV + xv1],
                                   g_table_t[(size_t)(HH + j0) * VV + xv1],
                                   g_table_t[(size_t)(j0 + 1) * VV + xv1],
                                   g_table_t[(size_t)(HH + j0 + 1) * VV + xv1]);
        } else {
            inpA_cur = make_float4(__ldcg(&g_in1[0][j0 * BB + grow0]),
                                   __ldcg(&g_in1[0][(HH + j0) * BB + grow0]),
                                   __ldcg(&g_in1[0][(j0 + 1) * BB + grow0]),
                                   __ldcg(&g_in1[0][(HH + j0 + 1) * BB + grow0]));
            inpB_cur = make_float4(__ldcg(&g_in1[0][j0 * BB + grow1]),
                                   __ldcg(&g_in1[0][(HH + j0) * BB + grow1]),
                                   __ldcg(&g_in1[0][(j0 + 1) * BB + grow1]),
                                   __ldcg(&g_in1[0][(HH + j0 + 1) * BB + grow1]));
        }
    }

    unsigned sidx = 0;
    for (int t = 0; t < TT; ++t) {
        float4 inpA_next = make_float4(0.f, 0.f, 0.f, 0.f);
        float4 inpB_next = make_float4(0.f, 0.f, 0.f, 0.f);
        for (int d = 0; d < 4; ++d) {
            // ---- ke group: poll its single producer counter, stage 8KB ----
            {
                unsigned tgt = 8u * (pbase + sidx);
                if (lt == 0) {
                    unsigned v;
                    do {
                        asm volatile("ld.acquire.gpu.global.u32 %0,[%1];"
                                     : "=r"(v) : "l"(grp_cnt) : "memory");
                    } while (v < tgt);
                }
                asm volatile("bar.sync %0, 64;" :: "r"(2 + ke) : "memory");
#pragma unroll
                for (int i2 = 0; i2 < 8; ++i2) {
                    int idx = lt + i2 * 64;             // 0..511
                    int kp  = qbase + (idx >> 4);
                    int i   = idx & 15;
                    reinterpret_cast<float4*>(s_pair)[kp * 16 + i] =
                        __ldcg(reinterpret_cast<const float4*>(
                            s_cur + (size_t)kp * 128 + rg * 64) + i);
                }
                asm volatile("bar.sync %0, 64;" :: "r"(2 + ke) : "memory");
            }

            // prefetch next-t input during compute
            if (d == 0 && ke == 0 && t + 1 < TT) {
                if (PASS == 0) {
                    int xv0 = x[(t + 1) * BB + grow0], xv1 = x[(t + 1) * BB + grow1];
                    inpA_next = make_float4(g_table_t[(size_t)j0 * VV + xv0],
                                            g_table_t[(size_t)(HH + j0) * VV + xv0],
                                            g_table_t[(size_t)(j0 + 1) * VV + xv0],
                                            g_table_t[(size_t)(HH + j0 + 1) * VV + xv0]);
                    inpB_next = make_float4(g_table_t[(size_t)j0 * VV + xv1],
                                            g_table_t[(size_t)(HH + j0) * VV + xv1],
                                            g_table_t[(size_t)(j0 + 1) * VV + xv1],
                                            g_table_t[(size_t)(HH + j0 + 1) * VV + xv1]);
                } else {
                    inpA_next = make_float4(__ldcg(&g_in1[t + 1][j0 * BB + grow0]),
                                            __ldcg(&g_in1[t + 1][(HH + j0) * BB + grow0]),
                                            __ldcg(&g_in1[t + 1][(j0 + 1) * BB + grow0]),
                                            __ldcg(&g_in1[t + 1][(HH + j0 + 1) * BB + grow0]));
                    inpB_next = make_float4(__ldcg(&g_in1[t + 1][j0 * BB + grow1]),
                                            __ldcg(&g_in1[t + 1][(HH + j0) * BB + grow1]),
                                            __ldcg(&g_in1[t + 1][(j0 + 1) * BB + grow1]),
                                            __ldcg(&g_in1[t + 1][(HH + j0 + 1) * BB + grow1]));
                }
            }

            // ---- register-tiled dot: 2 rows x 2 cols x 32 kp ----
            ull aH0r0 = 0, aG0r0 = 0, aH1r0 = 0, aG1r0 = 0;
            ull aH0r1 = 0, aG0r1 = 0, aH1r1 = 0, aG1r1 = 0;
            const ulonglong2* wq = w_pk + (size_t)d * 2048;
#pragma unroll
            for (int qq = 0; qq < 32; ++qq) {
                int q = qbase + qq;
                ull sv0 = sq[q * 32 + R0];
                ull sv1 = sq[q * 32 + R1];
                ulonglong2 wA = wq[q * 8 + 2 * cp];
                ulonglong2 wB = wq[q * 8 + 2 * cp + 1];
                aH0r0 = fma2(sv0, wA.x, aH0r0);
                aG0r0 = fma2(sv0, wA.y, aG0r0);
                aH1r0 = fma2(sv0, wB.x, aH1r0);
                aG1r0 = fma2(sv0, wB.y, aG1r0);
                aH0r1 = fma2(sv1, wA.x, aH0r1);
                aG0r1 = fma2(sv1, wA.y, aG0r1);
                aH1r1 = fma2(sv1, wB.x, aH1r1);
                aG1r1 = fma2(sv1, wB.y, aG1r1);
            }
            float2 pH0r0 = upk2(aH0r0), pG0r0 = upk2(aG0r0);
            float2 pH1r0 = upk2(aH1r0), pG1r0 = upk2(aG1r0);
            float2 pH0r1 = upk2(aH0r1), pG0r1 = upk2(aG0r1);
            float2 pH1r1 = upk2(aH1r1), pG1r1 = upk2(aG1r1);

            const int par = (int)(sidx & 1u);
            if (ke != 0) {
                // producers: publish partials, arrive (non-blocking), roll on
                float2* sc = scratch + (par * 7 + (ke - 1)) * 264;
                sc[(2 * cp) * 33 + R0]     = make_float2(pH0r0.x + pH0r0.y, pG0r0.x + pG0r0.y);
                sc[(2 * cp + 1) * 33 + R0] = make_float2(pH1r0.x + pH1r0.y, pG1r0.x + pG1r0.y);
                sc[(2 * cp) * 33 + R1]     = make_float2(pH0r1.x + pH0r1.y, pG0r1.x + pG0r1.y);
                sc[(2 * cp + 1) * 33 + R1] = make_float2(pH1r1.x + pH1r1.y, pG1r1.x + pG1r1.y);
                asm volatile("bar.arrive 11, 512;" ::: "memory");
            } else {
                // consumer group: wait for all partials of THIS step
                asm volatile("bar.sync 11, 512;" ::: "memory");

                float h0r0 = bh0[d] + pH0r0.x + pH0r0.y;
                float g0r0 = bg0[d] + pG0r0.x + pG0r0.y;
                float h1r0 = bh1[d] + pH1r0.x + pH1r0.y;
                float g1r0 = bg1[d] + pG1r0.x + pG1r0.y;
                float h0r1 = bh0[d] + pH0r1.x + pH0r1.y;
                float g0r1 = bg0[d] + pG0r1.x + pG0r1.y;
                float h1r1 = bh1[d] + pH1r1.x + pH1r1.y;
                float g1r1 = bg1[d] + pG1r1.x + pG1r1.y;
#pragma unroll
                for (int kk = 0; kk < 7; ++kk) {
                    const float2* sc = scratch + (par * 7 + kk) * 264;
                    float2 a0 = sc[(2 * cp) * 33 + R0];
                    float2 a1 = sc[(2 * cp + 1) * 33 + R0];
                    float2 b0 = sc[(2 * cp) * 33 + R1];
                    float2 b1 = sc[(2 * cp + 1) * 33 + R1];
                    h0r0 += a0.x; g0r0 += a0.y; h1r0 += a1.x; g1r0 += a1.y;
                    h0r1 += b0.x; g0r1 += b0.y; h1r1 += b1.x; g1r1 += b1.y;
                }
                if (d == 0) {
                    h0r0 += inpA_cur.x; g0r0 += inpA_cur.y;
                    h1r0 += inpA_cur.z; g1r0 += inpA_cur.w;
                    h0r1 += inpB_cur.x; g0r1 += inpB_cur.y;
                    h1r1 += inpB_cur.z; g1r1 += inpB_cur.w;
                }

                float gt;
                gt = 1.0f / (1.0f + expf(-g0r0));
                float sn00 = tanhf(h0r0) * gt + s_own0.x * (1.0f - gt);
                gt = 1.0f / (1.0f + expf(-g1r0));
                float sn10 = tanhf(h1r0) * gt + s_own0.y * (1.0f - gt);
                gt = 1.0f / (1.0f + expf(-g0r1));
                float sn01 = tanhf(h0r1) * gt + s_own1.x * (1.0f - gt);
                gt = 1.0f / (1.0f + expf(-g1r1));
                float sn11 = tanhf(h1r1) * gt + s_own1.y * (1.0f - gt);
                s_own0 = make_float2(sn00, sn10);
                s_own1 = make_float2(sn01, sn11);

                __stcg(reinterpret_cast<float2*>(s_nxt) + kpj * BB + grow0,
                       make_float2(sn00, sn10));
                __stcg(reinterpret_cast<float2*>(s_nxt) + kpj * BB + grow1,
                       make_float2(sn01, sn11));
                if (d == 3) {
                    float* ob = (PASS == 0) ? g_out0[t] : g_out1[t];
                    ob[j0 * BB + grow0]       = sn00;
                    ob[(j0 + 1) * BB + grow0] = sn10;
                    ob[j0 * BB + grow1]       = sn01;
                    ob[(j0 + 1) * BB + grow1] = sn11;
                }
                // leader-release: bar orders the group's stores before tid0's red
                asm volatile("bar.sync 10, 64;" ::: "memory");
                if (tid == 0) {
                    asm volatile("red.release.gpu.global.add.u32 [%0], 1;"
                                 :: "l"(my_cnt) : "memory");
                }
            }

            const float* tmp = s_nxt;
            s_nxt = (float*)s_cur;
            s_cur = tmp;
            ++sidx;
        }
        inpA_cur = inpA_next;
        inpB_cur = inpB_next;
    }
}

// ---------------------------------------------------------------------------
// g_in1[t][j][b] = sum_h g_out0[t][h][b] * w_in[1][h][j]   (FFMA2)
// ---------------------------------------------------------------------------
__global__ void k_inp1(const float* __restrict__ w_in) {
    int bid = blockIdx.x;
    int t   = bid >> 4;
    int jb  = bid & 15;
    int tid = threadIdx.x;
    int b   = tid & 63;
    int js  = tid >> 6;
    int j0  = jb * 64 + js * 16;

    ull acc[8];
#pragma unroll
    for (int i = 0; i < 8; ++i) acc[i] = pk2(0.f, 0.f);

    const float* o  = g_out0[t];
    const float* w1 = w_in + (size_t)EE * (2 * HH);
#pragma unroll 2
    for (int h = 0; h < HH; ++h) {
        ull svp = pkd(o[h * BB + b]);
        const ulonglong2* wr = reinterpret_cast<const ulonglong2*>(w1 + (size_t)h * (2 * HH) + j0);
        ulonglong2 q0 = wr[0], q1 = wr[1], q2 = wr[2], q3 = wr[3];
        acc[0] = fma2(svp, q0.x, acc[0]);  acc[1] = fma2(svp, q0.y, acc[1]);
        acc[2] = fma2(svp, q1.x, acc[2]);  acc[3] = fma2(svp, q1.y, acc[3]);
        acc[4] = fma2(svp, q2.x, acc[4]);  acc[5] = fma2(svp, q2.y, acc[5]);
        acc[6] = fma2(svp, q3.x, acc[6]);  acc[7] = fma2(svp, q3.y, acc[7]);
    }
#pragma unroll
    for (int i = 0; i < 8; ++i) {
        float2 v = upk2(acc[i]);
        g_in1[t][(j0 + 2 * i) * BB + b]     = v.x;
        g_in1[t][(j0 + 2 * i + 1) * BB + b] = v.y;
    }
}

// ---------------------------------------------------------------------------
__global__ void k_logits(const float* __restrict__ w_fc,
                         const float* __restrict__ b_fc,
                         float* __restrict__ out) {
    int bid = blockIdx.x;
    int t   = bid >> 2;
    int vb  = bid & 3;
    int tid = threadIdx.x;
    int b   = tid & 63;
    int vs  = tid >> 6;
    int v0  = vb * 64 + vs * 16;

    ull acc[8];
    const ulonglong2* bp = reinterpret_cast<const ulonglong2*>(b_fc + v0);
#pragma unroll
    for (int i = 0; i < 4; ++i) {
        ulonglong2 bq = bp[i];
        acc[2 * i] = bq.x; acc[2 * i + 1] = bq.y;
    }

    const float* o = g_out1[t];
#pragma unroll 2
    for (int h = 0; h < HH; ++h) {
        ull svp = pkd(o[h * BB + b]);
        const ulonglong2* wr = reinterpret_cast<const ulonglong2*>(w_fc + (size_t)h * VV + v0);
        ulonglong2 q0 = wr[0], q1 = wr[1], q2 = wr[2], q3 = wr[3];
        acc[0] = fma2(svp, q0.x, acc[0]);  acc[1] = fma2(svp, q0.y, acc[1]);
        acc[2] = fma2(svp, q1.x, acc[2]);  acc[3] = fma2(svp, q1.y, acc[3]);
        acc[4] = fma2(svp, q2.x, acc[4]);  acc[5] = fma2(svp, q2.y, acc[5]);
        acc[6] = fma2(svp, q3.x, acc[6]);  acc[7] = fma2(svp, q3.y, acc[7]);
    }

    ull* dst = reinterpret_cast<ull*>(out + ((size_t)(t * BB + b)) * VV + v0);
#pragma unroll
    for (int i = 0; i < 8; ++i) dst[i] = acc[i];
}

// ---------------------------------------------------------------------------
// s_final[l][b][h] from g_stateA in [kp][b][2] layout
// ---------------------------------------------------------------------------
__global__ void k_sfinal(float* __restrict__ out, int l) {
    int idx = blockIdx.x * blockDim.x + threadIdx.x;
    if (idx >= BB * HH) return;
    int b = idx >> 9;
    int h = idx & 511;
    out[(size_t)TT * BB * VV + (size_t)l * BB * HH + idx] =
        g_stateA[(h >> 1) * 128 + b * 2 + (h & 1)];
}

// ---------------------------------------------------------------------------
extern "C" void kernel_launch(void* const* d_in, const int* in_sizes, int n_in,
                              void* d_out, int out_size) {
    const int*   x    = (const int*)  d_in[0];
    const float* emb  = (const float*)d_in[1];
    const float* w_in = (const float*)d_in[2];
    const float* w_h  = (const float*)d_in[3];
    const float* b_h  = (const float*)d_in[4];
    const float* w_fc = (const float*)d_in[5];
    const float* b_fc = (const float*)d_in[6];
    float* out = (float*)d_out;

    const int smem_bytes = 131072 + 65536 + 29568;   // 226176 B
    static bool attr_done = false;
    if (!attr_done) {
        cudaFuncSetAttribute(k_rhn<0>, cudaFuncAttributeMaxDynamicSharedMemorySize, smem_bytes);
        cudaFuncSetAttribute(k_rhn<1>, cudaFuncAttributeMaxDynamicSharedMemorySize, smem_bytes);
        attr_done = true;
    }

    const bool has_sfinal = (out_size >= TT * BB * VV + 2 * BB * HH);

    k_reset<<<2, 256>>>();                                              // 1
    k_table<<<VV, 256>>>(emb, w_in);                                    // 2
    k_zero<<<(256 * BB * 2 + 255) / 256, 256>>>();                      // 3
    k_rhn<0><<<GRID_REC, NTH, smem_bytes>>>(x, w_h, b_h);               // 4 <- profiled
    if (has_sfinal)
        k_sfinal<<<(BB * HH + 255) / 256, 256>>>(out, 0);
    k_inp1<<<TT * 16, 256>>>(w_in);
    k_zero<<<(256 * BB * 2 + 255) / 256, 256>>>();
    k_rhn<1><<<GRID_REC, NTH, smem_bytes>>>(x, w_h, b_h);
    k_logits<<<TT * 4, 256>>>(w_fc, b_fc, out);
    if (has_sfinal)
        k_sfinal<<<(BB * HH + 255) / 256, 256>>>(out, 1);
}

// round 16
// speedup vs baseline: 2.5255x; 1.1271x over previous
#include <cuda_runtime.h>
#include <math.h>

#define TT 512
#define BB 64
#define VV 256
#define EE 512
#define HH 512

#define GRID_REC 128
#define NTH 512

typedef unsigned long long ull;
__device__ __forceinline__ ull pk2(float x, float y) {
    ull r; asm("mov.b64 %0,{%1,%2};" : "=l"(r) : "f"(x), "f"(y)); return r;
}
__device__ __forceinline__ ull pkd(float x) {
    ull r; asm("mov.b64 %0,{%1,%1};" : "=l"(r) : "f"(x)); return r;
}
__device__ __forceinline__ ull fma2(ull a, ull b, ull c) {
    ull d; asm("fma.rn.f32x2 %0,%1,%2,%3;" : "=l"(d) : "l"(a), "l"(b), "l"(c)); return d;
}
__device__ __forceinline__ float2 upk2(ull a) {
    float2 r; asm("mov.b64 {%0,%1},%2;" : "=f"(r.x), "=f"(r.y) : "l"(a)); return r;
}

// ---------------------------------------------------------------------------
// Static scratch.  State layout: [kp][b][2]  (k-pair interleaved, kp=h>>1)
// ---------------------------------------------------------------------------
__device__ float g_table_t[2 * HH * VV];          // [j][v] : (emb @ w_in[0])^T
__device__ float g_stateA[256 * BB * 2];          // state ping [kp][b][2]
__device__ float g_stateB[256 * BB * 2];          // state pong [kp][b][2]
__device__ float g_out0[TT][HH * BB];             // layer-0 outputs [t][h][b]
__device__ float g_out1[TT][HH * BB];             // layer-1 outputs [t][h][b]
__device__ float g_in1[TT][2 * HH * BB];          // layer-1 input preact [t][j][b]
__device__ unsigned g_cnt[2 * 8 * 32];            // [rg][keighth] counters

__global__ void k_reset() {
    int idx = blockIdx.x * blockDim.x + threadIdx.x;
    if (idx < 2 * 8 * 32) g_cnt[idx] = 0u;
}

__global__ void k_zero() {
    int idx = blockIdx.x * blockDim.x + threadIdx.x;
    if (idx < 256 * BB * 2) g_stateA[idx] = 0.0f;
}

// ---------------------------------------------------------------------------
__global__ void k_table(const float* __restrict__ emb,
                        const float* __restrict__ w_in) {
    int v = blockIdx.x;
    int j = threadIdx.x * 4;
    const float* er = emb + v * EE;
    float4 acc = make_float4(0.f, 0.f, 0.f, 0.f);
#pragma unroll 4
    for (int e = 0; e < EE; ++e) {
        float ev = er[e];
        float4 wv = *reinterpret_cast<const float4*>(w_in + (size_t)e * (2 * HH) + j);
        acc.x = fmaf(ev, wv.x, acc.x);
        acc.y = fmaf(ev, wv.y, acc.y);
        acc.z = fmaf(ev, wv.z, acc.z);
        acc.w = fmaf(ev, wv.w, acc.w);
    }
    g_table_t[(j + 0) * VV + v] = acc.x;
    g_table_t[(j + 1) * VV + v] = acc.y;
    g_table_t[(j + 2) * VV + v] = acc.z;
    g_table_t[(j + 3) * VV + v] = acc.w;
}

// ---------------------------------------------------------------------------
// Persistent RHN pass. 128 CTAs = 2 rowgroups x 64 colgroups.
// CTA tile 32 rows x 8 h-cols. 512 thr, 16 warps = 2 rowhalves x 8 k-eighths.
// Thread = 2 rows x 2 cols x 32 kp (8 FFMA2 accumulators).
// Staging via cp.async.cg (no STS, no reg round-trip).
// Producers publish float4 partials, bar.arrive, roll on; ke0 bar.sync,
// 14x LDS.128 reduce, epilogue, store, signal.
// ---------------------------------------------------------------------------
template <int PASS>
__global__ void __launch_bounds__(NTH, 1) k_rhn(
    const int*   __restrict__ x,
    const float* __restrict__ w_h,
    const float* __restrict__ b_h)
{
    extern __shared__ float smraw[];
    ulonglong2* w_pk     = reinterpret_cast<ulonglong2*>(smraw);         // [4][256][8] 131072 B
    float2*     s_pair   = reinterpret_cast<float2*>(smraw + 32768);     // [256][32]    65536 B
    float4*     scratch4 = reinterpret_cast<float4*>(smraw + 49152);     // [2][7][32][4] 28672 B

    const int tid  = threadIdx.x;
    const int cid  = blockIdx.x;
    const int rg   = cid >> 6;
    const int cg   = cid & 63;
    const int wid  = tid >> 5;
    const int lane = tid & 31;
    const int rh   = wid >> 3;          // rowhalf
    const int ke   = wid & 7;           // k-eighth 0..7
    const int rp   = lane >> 2;         // row-pair 0..7
    const int cp   = lane & 3;          // colpair 0..3
    const int R0   = rh * 16 + rp * 2;
    const int R1   = R0 + 1;
    const int grow0 = rg * 32 + R0;
    const int grow1 = grow0 + 1;
    const int j0   = cg * 8 + 2 * cp;
    const int kpj  = cg * 4 + cp;
    const int lt   = rh * 32 + lane;    // 0..63 within ke group
    const int qbase = ke * 32;

    unsigned smem_base;
    asm("{ .reg .u64 t; cvta.to.shared.u64 t, %1; cvt.u32.u64 %0, t; }"
        : "=r"(smem_base) : "l"(smraw));
    const unsigned spair_a = smem_base + 131072u;

    // ---- stage weights: w_pk[(d*256+kp)*8 + c] = {(wh0,wh1),(wg0,wg1)} ----
    for (int idx = tid; idx < 4 * 256 * 8; idx += NTH) {
        int c  = idx & 7;
        int kp = (idx >> 3) & 255;
        int d  = idx >> 11;
        const float* b0 = w_h + (((size_t)(PASS * 4 + d) * HH + 2 * kp) * (2 * HH)) + cg * 8 + c;
        const float* b1 = b0 + 2 * HH;
        w_pk[(d * 256 + kp) * 8 + c] =
            make_ulonglong2(pk2(b0[0], b1[0]), pk2(b0[HH], b1[HH]));
    }

    float bh0[4], bg0[4], bh1[4], bg1[4];
#pragma unroll
    for (int d = 0; d < 4; ++d) {
        const float* bb = b_h + (size_t)(PASS * 4 + d) * (2 * HH);
        bh0[d] = bb[j0];      bg0[d] = bb[HH + j0];
        bh1[d] = bb[j0 + 1];  bg1[d] = bb[HH + j0 + 1];
    }
    __syncthreads();

    const float* s_cur = g_stateA;
    float*       s_nxt = g_stateB;
    const unsigned pbase = (unsigned)PASS * 2048u;

    unsigned* my_cnt  = (unsigned*)&g_cnt[(rg * 8 + (cg >> 3)) * 32];
    unsigned* grp_cnt = (unsigned*)&g_cnt[(rg * 8 + ke) * 32];

    const ull* sq = reinterpret_cast<const ull*>(s_pair);

    float2 s_own0 = make_float2(0.f, 0.f);
    float2 s_own1 = make_float2(0.f, 0.f);

    // t=0 input prefetch (ke0 consumes)
    float4 inpA_cur = make_float4(0.f, 0.f, 0.f, 0.f);
    float4 inpB_cur = make_float4(0.f, 0.f, 0.f, 0.f);
    if (ke == 0) {
        if (PASS == 0) {
            int xv0 = x[0 * BB + grow0], xv1 = x[0 * BB + grow1];
            inpA_cur = make_float4(g_table_t[(size_t)j0 * VV + xv0],
                                   g_table_t[(size_t)(HH + j0) * VV + xv0],
                                   g_table_t[(size_t)(j0 + 1) * VV + xv0],
                                   g_table_t[(size_t)(HH + j0 + 1) * VV + xv0]);
            inpB_cur = make_float4(g_table_t[(size_t)j0 * VV + xv1],
                                   g_table_t[(size_t)(HH + j0) * VV + xv1],
                                   g_table_t[(size_t)(j0 + 1) * VV + xv1],
                                   g_table_t[(size_t)(HH + j0 + 1) * VV + xv1]);
        } else {
            inpA_cur = make_float4(__ldcg(&g_in1[0][j0 * BB + grow0]),
                                   __ldcg(&g_in1[0][(HH + j0) * BB + grow0]),
                                   __ldcg(&g_in1[0][(j0 + 1) * BB + grow0]),
                                   __ldcg(&g_in1[0][(HH + j0 + 1) * BB + grow0]));
            inpB_cur = make_float4(__ldcg(&g_in1[0][j0 * BB + grow1]),
                                   __ldcg(&g_in1[0][(HH + j0) * BB + grow1]),
                                   __ldcg(&g_in1[0][(j0 + 1) * BB + grow1]),
                                   __ldcg(&g_in1[0][(HH + j0 + 1) * BB + grow1]));
        }
    }

    unsigned sidx = 0;
    for (int t = 0; t < TT; ++t) {
        float4 inpA_next = make_float4(0.f, 0.f, 0.f, 0.f);
        float4 inpB_next = make_float4(0.f, 0.f, 0.f, 0.f);
        for (int d = 0; d < 4; ++d) {
            // ---- ke group: poll its producer counter, cp.async-stage 8KB ----
            {
                unsigned tgt = 8u * (pbase + sidx);
                if (lt == 0) {
                    unsigned v;
                    do {
                        asm volatile("ld.acquire.gpu.global.u32 %0,[%1];"
                                     : "=r"(v) : "l"(grp_cnt) : "memory");
                    } while (v < tgt);
                }
                asm volatile("bar.sync %0, 64;" :: "r"(2 + ke) : "memory");
#pragma unroll
                for (int i2 = 0; i2 < 8; ++i2) {
                    int idx = lt + i2 * 64;             // 0..511
                    int kp  = qbase + (idx >> 4);
                    int i   = idx & 15;
                    unsigned dst = spair_a + (unsigned)(kp * 16 + i) * 16u;
                    const float* src = s_cur + (size_t)kp * 128 + rg * 64 + i * 4;
                    asm volatile("cp.async.cg.shared.global [%0],[%1],16;"
                                 :: "r"(dst), "l"(src) : "memory");
                }
                asm volatile("cp.async.commit_group;" ::: "memory");
                asm volatile("cp.async.wait_group 0;" ::: "memory");
                asm volatile("bar.sync %0, 64;" :: "r"(2 + ke) : "memory");
            }

            // prefetch next-t input during compute
            if (d == 0 && ke == 0 && t + 1 < TT) {
                if (PASS == 0) {
                    int xv0 = x[(t + 1) * BB + grow0], xv1 = x[(t + 1) * BB + grow1];
                    inpA_next = make_float4(g_table_t[(size_t)j0 * VV + xv0],
                                            g_table_t[(size_t)(HH + j0) * VV + xv0],
                                            g_table_t[(size_t)(j0 + 1) * VV + xv0],
                                            g_table_t[(size_t)(HH + j0 + 1) * VV + xv0]);
                    inpB_next = make_float4(g_table_t[(size_t)j0 * VV + xv1],
                                            g_table_t[(size_t)(HH + j0) * VV + xv1],
                                            g_table_t[(size_t)(j0 + 1) * VV + xv1],
                                            g_table_t[(size_t)(HH + j0 + 1) * VV + xv1]);
                } else {
                    inpA_next = make_float4(__ldcg(&g_in1[t + 1][j0 * BB + grow0]),
                                            __ldcg(&g_in1[t + 1][(HH + j0) * BB + grow0]),
                                            __ldcg(&g_in1[t + 1][(j0 + 1) * BB + grow0]),
                                            __ldcg(&g_in1[t + 1][(HH + j0 + 1) * BB + grow0]));
                    inpB_next = make_float4(__ldcg(&g_in1[t + 1][j0 * BB + grow1]),
                                            __ldcg(&g_in1[t + 1][(HH + j0) * BB + grow1]),
                                            __ldcg(&g_in1[t + 1][(j0 + 1) * BB + grow1]),
                                            __ldcg(&g_in1[t + 1][(HH + j0 + 1) * BB + grow1]));
                }
            }

            // ---- register-tiled dot: 2 rows x 2 cols x 32 kp ----
            ull aH0r0 = 0, aG0r0 = 0, aH1r0 = 0, aG1r0 = 0;
            ull aH0r1 = 0, aG0r1 = 0, aH1r1 = 0, aG1r1 = 0;
            const ulonglong2* wq = w_pk + (size_t)d * 2048;
#pragma unroll
            for (int qq = 0; qq < 32; ++qq) {
                int q = qbase + qq;
                ull sv0 = sq[q * 32 + R0];
                ull sv1 = sq[q * 32 + R1];
                ulonglong2 wA = wq[q * 8 + 2 * cp];
                ulonglong2 wB = wq[q * 8 + 2 * cp + 1];
                aH0r0 = fma2(sv0, wA.x, aH0r0);
                aG0r0 = fma2(sv0, wA.y, aG0r0);
                aH1r0 = fma2(sv0, wB.x, aH1r0);
                aG1r0 = fma2(sv0, wB.y, aG1r0);
                aH0r1 = fma2(sv1, wA.x, aH0r1);
                aG0r1 = fma2(sv1, wA.y, aG0r1);
                aH1r1 = fma2(sv1, wB.x, aH1r1);
                aG1r1 = fma2(sv1, wB.y, aG1r1);
            }
            float2 pH0r0 = upk2(aH0r0), pG0r0 = upk2(aG0r0);
            float2 pH1r0 = upk2(aH1r0), pG1r0 = upk2(aG1r0);
            float2 pH0r1 = upk2(aH0r1), pG0r1 = upk2(aG0r1);
            float2 pH1r1 = upk2(aH1r1), pG1r1 = upk2(aG1r1);

            const int par = (int)(sidx & 1u);
            if (ke != 0) {
                // producers: publish float4 partials, arrive, roll on
                float4* sc = scratch4 + (par * 7 + (ke - 1)) * 128;
                sc[R0 * 4 + cp] = make_float4(pH0r0.x + pH0r0.y, pG0r0.x + pG0r0.y,
                                              pH1r0.x + pH1r0.y, pG1r0.x + pG1r0.y);
                sc[R1 * 4 + cp] = make_float4(pH0r1.x + pH0r1.y, pG0r1.x + pG0r1.y,
                                              pH1r1.x + pH1r1.y, pG1r1.x + pG1r1.y);
                asm volatile("bar.arrive 11, 512;" ::: "memory");
            } else {
                asm volatile("bar.sync 11, 512;" ::: "memory");

                float h0r0 = bh0[d] + pH0r0.x + pH0r0.y;
                float g0r0 = bg0[d] + pG0r0.x + pG0r0.y;
                float h1r0 = bh1[d] + pH1r0.x + pH1r0.y;
                float g1r0 = bg1[d] + pG1r0.x + pG1r0.y;
                float h0r1 = bh0[d] + pH0r1.x + pH0r1.y;
                float g0r1 = bg0[d] + pG0r1.x + pG0r1.y;
                float h1r1 = bh1[d] + pH1r1.x + pH1r1.y;
                float g1r1 = bg1[d] + pG1r1.x + pG1r1.y;
#pragma unroll
                for (int kk = 0; kk < 7; ++kk) {
                    const float4* sc = scratch4 + (par * 7 + kk) * 128;
                    float4 a = sc[R0 * 4 + cp];
                    float4 b = sc[R1 * 4 + cp];
                    h0r0 += a.x; g0r0 += a.y; h1r0 += a.z; g1r0 += a.w;
                    h0r1 += b.x; g0r1 += b.y; h1r1 += b.z; g1r1 += b.w;
                }
                if (d == 0) {
                    h0r0 += inpA_cur.x; g0r0 += inpA_cur.y;
                    h1r0 += inpA_cur.z; g1r0 += inpA_cur.w;
                    h0r1 += inpB_cur.x; g0r1 += inpB_cur.y;
                    h1r1 += inpB_cur.z; g1r1 += inpB_cur.w;
                }

                float gt;
                gt = 1.0f / (1.0f + expf(-g0r0));
                float sn00 = tanhf(h0r0) * gt + s_own0.x * (1.0f - gt);
                gt = 1.0f / (1.0f + expf(-g1r0));
                float sn10 = tanhf(h1r0) * gt + s_own0.y * (1.0f - gt);
                gt = 1.0f / (1.0f + expf(-g0r1));
                float sn01 = tanhf(h0r1) * gt + s_own1.x * (1.0f - gt);
                gt = 1.0f / (1.0f + expf(-g1r1));
                float sn11 = tanhf(h1r1) * gt + s_own1.y * (1.0f - gt);
                s_own0 = make_float2(sn00, sn10);
                s_own1 = make_float2(sn01, sn11);

                __stcg(reinterpret_cast<float2*>(s_nxt) + kpj * BB + grow0,
                       make_float2(sn00, sn10));
                __stcg(reinterpret_cast<float2*>(s_nxt) + kpj * BB + grow1,
                       make_float2(sn01, sn11));
                if (d == 3) {
                    float* ob = (PASS == 0) ? g_out0[t] : g_out1[t];
                    ob[j0 * BB + grow0]       = sn00;
                    ob[(j0 + 1) * BB + grow0] = sn10;
                    ob[j0 * BB + grow1]       = sn01;
                    ob[(j0 + 1) * BB + grow1] = sn11;
                }
                asm volatile("bar.sync 10, 64;" ::: "memory");
                if (tid == 0) {
                    asm volatile("red.release.gpu.global.add.u32 [%0], 1;"
                                 :: "l"(my_cnt) : "memory");
                }
            }

            const float* tmp = s_nxt;
            s_nxt = (float*)s_cur;
            s_cur = tmp;
            ++sidx;
        }
        inpA_cur = inpA_next;
        inpB_cur = inpB_next;
    }
}

// ---------------------------------------------------------------------------
// g_in1[t][j][b] = sum_h g_out0[t][h][b] * w_in[1][h][j]   (FFMA2)
// ---------------------------------------------------------------------------
__global__ void k_inp1(const float* __restrict__ w_in) {
    int bid = blockIdx.x;
    int t   = bid >> 4;
    int jb  = bid & 15;
    int tid = threadIdx.x;
    int b   = tid & 63;
    int js  = tid >> 6;
    int j0  = jb * 64 + js * 16;

    ull acc[8];
#pragma unroll
    for (int i = 0; i < 8; ++i) acc[i] = pk2(0.f, 0.f);

    const float* o  = g_out0[t];
    const float* w1 = w_in + (size_t)EE * (2 * HH);
#pragma unroll 2
    for (int h = 0; h < HH; ++h) {
        ull svp = pkd(o[h * BB + b]);
        const ulonglong2* wr = reinterpret_cast<const ulonglong2*>(w1 + (size_t)h * (2 * HH) + j0);
        ulonglong2 q0 = wr[0], q1 = wr[1], q2 = wr[2], q3 = wr[3];
        acc[0] = fma2(svp, q0.x, acc[0]);  acc[1] = fma2(svp, q0.y, acc[1]);
        acc[2] = fma2(svp, q1.x, acc[2]);  acc[3] = fma2(svp, q1.y, acc[3]);
        acc[4] = fma2(svp, q2.x, acc[4]);  acc[5] = fma2(svp, q2.y, acc[5]);
        acc[6] = fma2(svp, q3.x, acc[6]);  acc[7] = fma2(svp, q3.y, acc[7]);
    }
#pragma unroll
    for (int i = 0; i < 8; ++i) {
        float2 v = upk2(acc[i]);
        g_in1[t][(j0 + 2 * i) * BB + b]     = v.x;
        g_in1[t][(j0 + 2 * i + 1) * BB + b] = v.y;
    }
}

// ---------------------------------------------------------------------------
__global__ void k_logits(const float* __restrict__ w_fc,
                         const float* __restrict__ b_fc,
                         float* __restrict__ out) {
    int bid = blockIdx.x;
    int t   = bid >> 2;
    int vb  = bid & 3;
    int tid = threadIdx.x;
    int b   = tid & 63;
    int vs  = tid >> 6;
    int v0  = vb * 64 + vs * 16;

    ull acc[8];
    const ulonglong2* bp = reinterpret_cast<const ulonglong2*>(b_fc + v0);
#pragma unroll
    for (int i = 0; i < 4; ++i) {
        ulonglong2 bq = bp[i];
        acc[2 * i] = bq.x; acc[2 * i + 1] = bq.y;
    }

    const float* o = g_out1[t];
#pragma unroll 2
    for (int h = 0; h < HH; ++h) {
        ull svp = pkd(o[h * BB + b]);
        const ulonglong2* wr = reinterpret_cast<const ulonglong2*>(w_fc + (size_t)h * VV + v0);
        ulonglong2 q0 = wr[0], q1 = wr[1], q2 = wr[2], q3 = wr[3];
        acc[0] = fma2(svp, q0.x, acc[0]);  acc[1] = fma2(svp, q0.y, acc[1]);
        acc[2] = fma2(svp, q1.x, acc[2]);  acc[3] = fma2(svp, q1.y, acc[3]);
        acc[4] = fma2(svp, q2.x, acc[4]);  acc[5] = fma2(svp, q2.y, acc[5]);
        acc[6] = fma2(svp, q3.x, acc[6]);  acc[7] = fma2(svp, q3.y, acc[7]);
    }

    ull* dst = reinterpret_cast<ull*>(out + ((size_t)(t * BB + b)) * VV + v0);
#pragma unroll
    for (int i = 0; i < 8; ++i) dst[i] = acc[i];
}

// ---------------------------------------------------------------------------
// s_final[l][b][h] from g_stateA in [kp][b][2] layout
// ---------------------------------------------------------------------------
__global__ void k_sfinal(float* __restrict__ out, int l) {
    int idx = blockIdx.x * blockDim.x + threadIdx.x;
    if (idx >= BB * HH) return;
    int b = idx >> 9;
    int h = idx & 511;
    out[(size_t)TT * BB * VV + (size_t)l * BB * HH + idx] =
        g_stateA[(h >> 1) * 128 + b * 2 + (h & 1)];
}

// ---------------------------------------------------------------------------
extern "C" void kernel_launch(void* const* d_in, const int* in_sizes, int n_in,
                              void* d_out, int out_size) {
    const int*   x    = (const int*)  d_in[0];
    const float* emb  = (const float*)d_in[1];
    const float* w_in = (const float*)d_in[2];
    const float* w_h  = (const float*)d_in[3];
    const float* b_h  = (const float*)d_in[4];
    const float* w_fc = (const float*)d_in[5];
    const float* b_fc = (const float*)d_in[6];
    float* out = (float*)d_out;

    const int smem_bytes = 131072 + 65536 + 28672;   // 225280 B
    static bool attr_done = false;
    if (!attr_done) {
        cudaFuncSetAttribute(k_rhn<0>, cudaFuncAttributeMaxDynamicSharedMemorySize, smem_bytes);
        cudaFuncSetAttribute(k_rhn<1>, cudaFuncAttributeMaxDynamicSharedMemorySize, smem_bytes);
        attr_done = true;
    }

    const bool has_sfinal = (out_size >= TT * BB * VV + 2 * BB * HH);

    k_reset<<<2, 256>>>();                                              // 1
    k_table<<<VV, 256>>>(emb, w_in);                                    // 2
    k_zero<<<(256 * BB * 2 + 255) / 256, 256>>>();                      // 3
    k_rhn<0><<<GRID_REC, NTH, smem_bytes>>>(x, w_h, b_h);               // 4 <- profiled
    if (has_sfinal)
        k_sfinal<<<(BB * HH + 255) / 256, 256>>>(out, 0);
    k_inp1<<<TT * 16, 256>>>(w_in);
    k_zero<<<(256 * BB * 2 + 255) / 256, 256>>>();
    k_rhn<1><<<GRID_REC, NTH, smem_bytes>>>(x, w_h, b_h);
    k_logits<<<TT * 4, 256>>>(w_fc, b_fc, out);
    if (has_sfinal)
        k_sfinal<<<(BB * HH + 255) / 256, 256>>>(out, 1);
}

// round 17
// speedup vs baseline: 2.5971x; 1.0284x over previous
#include <cuda_runtime.h>
#include <math.h>

#define TT 512
#define BB 64
#define VV 256
#define EE 512
#define HH 512

#define GRID_REC 128
#define NTH 512

typedef unsigned long long ull;
__device__ __forceinline__ ull pk2(float x, float y) {
    ull r; asm("mov.b64 %0,{%1,%2};" : "=l"(r) : "f"(x), "f"(y)); return r;
}
__device__ __forceinline__ ull pkd(float x) {
    ull r; asm("mov.b64 %0,{%1,%1};" : "=l"(r) : "f"(x)); return r;
}
__device__ __forceinline__ ull fma2(ull a, ull b, ull c) {
    ull d; asm("fma.rn.f32x2 %0,%1,%2,%3;" : "=l"(d) : "l"(a), "l"(b), "l"(c)); return d;
}
__device__ __forceinline__ float2 upk2(ull a) {
    float2 r; asm("mov.b64 {%0,%1},%2;" : "=f"(r.x), "=f"(r.y) : "l"(a)); return r;
}

// fast sigmoid / tanh via MUFU (rel err ~2^-21, << 1e-3 budget)
__device__ __forceinline__ float fsig(float x) {
    return __fdividef(1.0f, 1.0f + __expf(-x));
}
__device__ __forceinline__ float ftanh(float x) {
    return __fdividef(2.0f, 1.0f + __expf(-2.0f * x)) - 1.0f;
}

// ---------------------------------------------------------------------------
// Static scratch.  State layout: [kp][b][2]  (k-pair interleaved, kp=h>>1)
// ---------------------------------------------------------------------------
__device__ float g_table_t[2 * HH * VV];          // [j][v] : (emb @ w_in[0])^T
__device__ float g_stateA[256 * BB * 2];          // state ping [kp][b][2]
__device__ float g_stateB[256 * BB * 2];          // state pong [kp][b][2]
__device__ float g_out0[TT][HH * BB];             // layer-0 outputs [t][h][b]
__device__ float g_out1[TT][HH * BB];             // layer-1 outputs [t][h][b]
__device__ float g_in1[TT][2 * HH * BB];          // layer-1 input preact [t][j][b]
__device__ unsigned g_cnt[2 * 8 * 32];            // [rg][keighth] counters

__global__ void k_reset() {
    int idx = blockIdx.x * blockDim.x + threadIdx.x;
    if (idx < 2 * 8 * 32) g_cnt[idx] = 0u;
}

__global__ void k_zero() {
    int idx = blockIdx.x * blockDim.x + threadIdx.x;
    if (idx < 256 * BB * 2) g_stateA[idx] = 0.0f;
}

// ---------------------------------------------------------------------------
__global__ void k_table(const float* __restrict__ emb,
                        const float* __restrict__ w_in) {
    int v = blockIdx.x;
    int j = threadIdx.x * 4;
    const float* er = emb + v * EE;
    float4 acc = make_float4(0.f, 0.f, 0.f, 0.f);
#pragma unroll 4
    for (int e = 0; e < EE; ++e) {
        float ev = er[e];
        float4 wv = *reinterpret_cast<const float4*>(w_in + (size_t)e * (2 * HH) + j);
        acc.x = fmaf(ev, wv.x, acc.x);
        acc.y = fmaf(ev, wv.y, acc.y);
        acc.z = fmaf(ev, wv.z, acc.z);
        acc.w = fmaf(ev, wv.w, acc.w);
    }
    g_table_t[(j + 0) * VV + v] = acc.x;
    g_table_t[(j + 1) * VV + v] = acc.y;
    g_table_t[(j + 2) * VV + v] = acc.z;
    g_table_t[(j + 3) * VV + v] = acc.w;
}

// ---------------------------------------------------------------------------
// Persistent RHN pass. 128 CTAs = 2 rowgroups x 64 colgroups.
// CTA tile 32 rows x 8 h-cols. 512 thr, 16 warps = 2 rowhalves x 8 k-eighths.
// Thread = 2 rows x 2 cols x 32 kp (8 FFMA2 accumulators).
// Staging via cp.async.cg; state row-pair read as ONE LDS.128 (R0,R1 adjacent).
// Producers publish float4 partials, bar.arrive, roll on; ke0 bar.sync,
// LDS.128 reduce, fast-math epilogue, store, signal.
// ---------------------------------------------------------------------------
template <int PASS>
__global__ void __launch_bounds__(NTH, 1) k_rhn(
    const int*   __restrict__ x,
    const float* __restrict__ w_h,
    const float* __restrict__ b_h)
{
    extern __shared__ float smraw[];
    ulonglong2* w_pk     = reinterpret_cast<ulonglong2*>(smraw);         // [4][256][8] 131072 B
    float2*     s_pair   = reinterpret_cast<float2*>(smraw + 32768);     // [256][32]    65536 B
    float4*     scratch4 = reinterpret_cast<float4*>(smraw + 49152);     // [2][7][32][4] 28672 B

    const int tid  = threadIdx.x;
    const int cid  = blockIdx.x;
    const int rg   = cid >> 6;
    const int cg   = cid & 63;
    const int wid  = tid >> 5;
    const int lane = tid & 31;
    const int rh   = wid >> 3;          // rowhalf
    const int ke   = wid & 7;           // k-eighth 0..7
    const int rp   = lane >> 2;         // row-pair 0..7
    const int cp   = lane & 3;          // colpair 0..3
    const int R0   = rh * 16 + rp * 2;
    const int R1   = R0 + 1;
    const int grow0 = rg * 32 + R0;
    const int grow1 = grow0 + 1;
    const int j0   = cg * 8 + 2 * cp;
    const int kpj  = cg * 4 + cp;
    const int lt   = rh * 32 + lane;    // 0..63 within ke group
    const int qbase = ke * 32;

    unsigned smem_base;
    asm("{ .reg .u64 t; cvta.to.shared.u64 t, %1; cvt.u32.u64 %0, t; }"
        : "=r"(smem_base) : "l"(smraw));
    const unsigned spair_a = smem_base + 131072u;

    // ---- stage weights: w_pk[(d*256+kp)*8 + c] = {(wh0,wh1),(wg0,wg1)} ----
    for (int idx = tid; idx < 4 * 256 * 8; idx += NTH) {
        int c  = idx & 7;
        int kp = (idx >> 3) & 255;
        int d  = idx >> 11;
        const float* b0 = w_h + (((size_t)(PASS * 4 + d) * HH + 2 * kp) * (2 * HH)) + cg * 8 + c;
        const float* b1 = b0 + 2 * HH;
        w_pk[(d * 256 + kp) * 8 + c] =
            make_ulonglong2(pk2(b0[0], b1[0]), pk2(b0[HH], b1[HH]));
    }

    float bh0[4], bg0[4], bh1[4], bg1[4];
#pragma unroll
    for (int d = 0; d < 4; ++d) {
        const float* bb = b_h + (size_t)(PASS * 4 + d) * (2 * HH);
        bh0[d] = bb[j0];      bg0[d] = bb[HH + j0];
        bh1[d] = bb[j0 + 1];  bg1[d] = bb[HH + j0 + 1];
    }
    __syncthreads();

    const float* s_cur = g_stateA;
    float*       s_nxt = g_stateB;
    const unsigned pbase = (unsigned)PASS * 2048u;

    unsigned* my_cnt  = (unsigned*)&g_cnt[(rg * 8 + (cg >> 3)) * 32];
    unsigned* grp_cnt = (unsigned*)&g_cnt[(rg * 8 + ke) * 32];

    const ulonglong2* sq2 = reinterpret_cast<const ulonglong2*>(s_pair);
    const int svbase = R0 >> 1;          // ulonglong2 index within a kp row-block

    float2 s_own0 = make_float2(0.f, 0.f);
    float2 s_own1 = make_float2(0.f, 0.f);

    // t=0 input prefetch (ke0 consumes)
    float4 inpA_cur = make_float4(0.f, 0.f, 0.f, 0.f);
    float4 inpB_cur = make_float4(0.f, 0.f, 0.f, 0.f);
    if (ke == 0) {
        if (PASS == 0) {
            int xv0 = x[0 * BB + grow0], xv1 = x[0 * BB + grow1];
            inpA_cur = make_float4(g_table_t[(size_t)j0 * VV + xv0],
                                   g_table_t[(size_t)(HH + j0) * VV + xv0],
                                   g_table_t[(size_t)(j0 + 1) * VV + xv0],
                                   g_table_t[(size_t)(HH + j0 + 1) * VV + xv0]);
            inpB_cur = make_float4(g_table_t[(size_t)j0 * VV + xv1],
                                   g_table_t[(size_t)(HH + j0) * VV + xv1],
                                   g_table_t[(size_t)(j0 + 1) * VV + xv1],
                                   g_table_t[(size_t)(HH + j0 + 1) * VV + xv1]);
        } else {
            inpA_cur = make_float4(__ldcg(&g_in1[0][j0 * BB + grow0]),
                                   __ldcg(&g_in1[0][(HH + j0) * BB + grow0]),
                                   __ldcg(&g_in1[0][(j0 + 1) * BB + grow0]),
                                   __ldcg(&g_in1[0][(HH + j0 + 1) * BB + grow0]));
            inpB_cur = make_float4(__ldcg(&g_in1[0][j0 * BB + grow1]),
                                   __ldcg(&g_in1[0][(HH + j0) * BB + grow1]),
                                   __ldcg(&g_in1[0][(j0 + 1) * BB + grow1]),
                                   __ldcg(&g_in1[0][(HH + j0 + 1) * BB + grow1]));
        }
    }

    unsigned sidx = 0;
    for (int t = 0; t < TT; ++t) {
        float4 inpA_next = make_float4(0.f, 0.f, 0.f, 0.f);
        float4 inpB_next = make_float4(0.f, 0.f, 0.f, 0.f);
        for (int d = 0; d < 4; ++d) {
            // ---- ke group: poll its producer counter, cp.async-stage 8KB ----
            {
                unsigned tgt = 8u * (pbase + sidx);
                if (lt == 0) {
                    unsigned v;
                    do {
                        asm volatile("ld.acquire.gpu.global.u32 %0,[%1];"
                                     : "=r"(v) : "l"(grp_cnt) : "memory");
                    } while (v < tgt);
                }
                asm volatile("bar.sync %0, 64;" :: "r"(2 + ke) : "memory");
#pragma unroll
                for (int i2 = 0; i2 < 8; ++i2) {
                    int idx = lt + i2 * 64;             // 0..511
                    int kp  = qbase + (idx >> 4);
                    int i   = idx & 15;
                    unsigned dst = spair_a + (unsigned)(kp * 16 + i) * 16u;
                    const float* src = s_cur + (size_t)kp * 128 + rg * 64 + i * 4;
                    asm volatile("cp.async.cg.shared.global [%0],[%1],16;"
                                 :: "r"(dst), "l"(src) : "memory");
                }
                asm volatile("cp.async.commit_group;" ::: "memory");
                asm volatile("cp.async.wait_group 0;" ::: "memory");
                asm volatile("bar.sync %0, 64;" :: "r"(2 + ke) : "memory");
            }

            // prefetch next-t input during compute
            if (d == 0 && ke == 0 && t + 1 < TT) {
                if (PASS == 0) {
                    int xv0 = x[(t + 1) * BB + grow0], xv1 = x[(t + 1) * BB + grow1];
                    inpA_next = make_float4(g_table_t[(size_t)j0 * VV + xv0],
                                            g_table_t[(size_t)(HH + j0) * VV + xv0],
                                            g_table_t[(size_t)(j0 + 1) * VV + xv0],
                                            g_table_t[(size_t)(HH + j0 + 1) * VV + xv0]);
                    inpB_next = make_float4(g_table_t[(size_t)j0 * VV + xv1],
                                            g_table_t[(size_t)(HH + j0) * VV + xv1],
                                            g_table_t[(size_t)(j0 + 1) * VV + xv1],
                                            g_table_t[(size_t)(HH + j0 + 1) * VV + xv1]);
                } else {
                    inpA_next = make_float4(__ldcg(&g_in1[t + 1][j0 * BB + grow0]),
                                            __ldcg(&g_in1[t + 1][(HH + j0) * BB + grow0]),
                                            __ldcg(&g_in1[t + 1][(j0 + 1) * BB + grow0]),
                                            __ldcg(&g_in1[t + 1][(HH + j0 + 1) * BB + grow0]));
                    inpB_next = make_float4(__ldcg(&g_in1[t + 1][j0 * BB + grow1]),
                                            __ldcg(&g_in1[t + 1][(HH + j0) * BB + grow1]),
                                            __ldcg(&g_in1[t + 1][(j0 + 1) * BB + grow1]),
                                            __ldcg(&g_in1[t + 1][(HH + j0 + 1) * BB + grow1]));
                }
            }

            // ---- register-tiled dot: 2 rows x 2 cols x 32 kp ----
            // state rows R0,R1 fetched as ONE LDS.128 (adjacent in [kp][b][2])
            ull aH0r0 = 0, aG0r0 = 0, aH1r0 = 0, aG1r0 = 0;
            ull aH0r1 = 0, aG0r1 = 0, aH1r1 = 0, aG1r1 = 0;
            const ulonglong2* wq = w_pk + (size_t)d * 2048;
#pragma unroll
            for (int qq = 0; qq < 32; ++qq) {
                int q = qbase + qq;
                ulonglong2 sv = sq2[q * 16 + svbase];   // {row R0 pair, row R1 pair}
                ulonglong2 wA = wq[q * 8 + 2 * cp];
                ulonglong2 wB = wq[q * 8 + 2 * cp + 1];
                aH0r0 = fma2(sv.x, wA.x, aH0r0);
                aG0r0 = fma2(sv.x, wA.y, aG0r0);
                aH1r0 = fma2(sv.x, wB.x, aH1r0);
                aG1r0 = fma2(sv.x, wB.y, aG1r0);
                aH0r1 = fma2(sv.y, wA.x, aH0r1);
                aG0r1 = fma2(sv.y, wA.y, aG0r1);
                aH1r1 = fma2(sv.y, wB.x, aH1r1);
                aG1r1 = fma2(sv.y, wB.y, aG1r1);
            }
            float2 pH0r0 = upk2(aH0r0), pG0r0 = upk2(aG0r0);
            float2 pH1r0 = upk2(aH1r0), pG1r0 = upk2(aG1r0);
            float2 pH0r1 = upk2(aH0r1), pG0r1 = upk2(aG0r1);
            float2 pH1r1 = upk2(aH1r1), pG1r1 = upk2(aG1r1);

            const int par = (int)(sidx & 1u);
            if (ke != 0) {
                // producers: publish float4 partials, arrive, roll on
                float4* sc = scratch4 + (par * 7 + (ke - 1)) * 128;
                sc[R0 * 4 + cp] = make_float4(pH0r0.x + pH0r0.y, pG0r0.x + pG0r0.y,
                                              pH1r0.x + pH1r0.y, pG1r0.x + pG1r0.y);
                sc[R1 * 4 + cp] = make_float4(pH0r1.x + pH0r1.y, pG0r1.x + pG0r1.y,
                                              pH1r1.x + pH1r1.y, pG1r1.x + pG1r1.y);
                asm volatile("bar.arrive 11, 512;" ::: "memory");
            } else {
                asm volatile("bar.sync 11, 512;" ::: "memory");

                float h0r0 = bh0[d] + pH0r0.x + pH0r0.y;
                float g0r0 = bg0[d] + pG0r0.x + pG0r0.y;
                float h1r0 = bh1[d] + pH1r0.x + pH1r0.y;
                float g1r0 = bg1[d] + pG1r0.x + pG1r0.y;
                float h0r1 = bh0[d] + pH0r1.x + pH0r1.y;
                float g0r1 = bg0[d] + pG0r1.x + pG0r1.y;
                float h1r1 = bh1[d] + pH1r1.x + pH1r1.y;
                float g1r1 = bg1[d] + pG1r1.x + pG1r1.y;
#pragma unroll
                for (int kk = 0; kk < 7; ++kk) {
                    const float4* sc = scratch4 + (par * 7 + kk) * 128;
                    float4 a = sc[R0 * 4 + cp];
                    float4 b = sc[R1 * 4 + cp];
                    h0r0 += a.x; g0r0 += a.y; h1r0 += a.z; g1r0 += a.w;
                    h0r1 += b.x; g0r1 += b.y; h1r1 += b.z; g1r1 += b.w;
                }
                if (d == 0) {
                    h0r0 += inpA_cur.x; g0r0 += inpA_cur.y;
                    h1r0 += inpA_cur.z; g1r0 += inpA_cur.w;
                    h0r1 += inpB_cur.x; g0r1 += inpB_cur.y;
                    h1r1 += inpB_cur.z; g1r1 += inpB_cur.w;
                }

                float gt;
                gt = fsig(g0r0);
                float sn00 = ftanh(h0r0) * gt + s_own0.x * (1.0f - gt);
                gt = fsig(g1r0);
                float sn10 = ftanh(h1r0) * gt + s_own0.y * (1.0f - gt);
                gt = fsig(g0r1);
                float sn01 = ftanh(h0r1) * gt + s_own1.x * (1.0f - gt);
                gt = fsig(g1r1);
                float sn11 = ftanh(h1r1) * gt + s_own1.y * (1.0f - gt);
                s_own0 = make_float2(sn00, sn10);
                s_own1 = make_float2(sn01, sn11);

                __stcg(reinterpret_cast<float2*>(s_nxt) + kpj * BB + grow0,
                       make_float2(sn00, sn10));
                __stcg(reinterpret_cast<float2*>(s_nxt) + kpj * BB + grow1,
                       make_float2(sn01, sn11));
                if (d == 3) {
                    float* ob = (PASS == 0) ? g_out0[t] : g_out1[t];
                    ob[j0 * BB + grow0]       = sn00;
                    ob[(j0 + 1) * BB + grow0] = sn10;
                    ob[j0 * BB + grow1]       = sn01;
                    ob[(j0 + 1) * BB + grow1] = sn11;
                }
                asm volatile("bar.sync 10, 64;" ::: "memory");
                if (tid == 0) {
                    asm volatile("red.release.gpu.global.add.u32 [%0], 1;"
                                 :: "l"(my_cnt) : "memory");
                }
            }

            const float* tmp = s_nxt;
            s_nxt = (float*)s_cur;
            s_cur = tmp;
            ++sidx;
        }
        inpA_cur = inpA_next;
        inpB_cur = inpB_next;
    }
}

// ---------------------------------------------------------------------------
// g_in1[t][j][b] = sum_h g_out0[t][h][b] * w_in[1][h][j]   (FFMA2)
// ---------------------------------------------------------------------------
__global__ void k_inp1(const float* __restrict__ w_in) {
    int bid = blockIdx.x;
    int t   = bid >> 4;
    int jb  = bid & 15;
    int tid = threadIdx.x;
    int b   = tid & 63;
    int js  = tid >> 6;
    int j0  = jb * 64 + js * 16;

    ull acc[8];
#pragma unroll
    for (int i = 0; i < 8; ++i) acc[i] = pk2(0.f, 0.f);

    const float* o  = g_out0[t];
    const float* w1 = w_in + (size_t)EE * (2 * HH);
#pragma unroll 2
    for (int h = 0; h < HH; ++h) {
        ull svp = pkd(o[h * BB + b]);
        const ulonglong2* wr = reinterpret_cast<const ulonglong2*>(w1 + (size_t)h * (2 * HH) + j0);
        ulonglong2 q0 = wr[0], q1 = wr[1], q2 = wr[2], q3 = wr[3];
        acc[0] = fma2(svp, q0.x, acc[0]);  acc[1] = fma2(svp, q0.y, acc[1]);
        acc[2] = fma2(svp, q1.x, acc[2]);  acc[3] = fma2(svp, q1.y, acc[3]);
        acc[4] = fma2(svp, q2.x, acc[4]);  acc[5] = fma2(svp, q2.y, acc[5]);
        acc[6] = fma2(svp, q3.x, acc[6]);  acc[7] = fma2(svp, q3.y, acc[7]);
    }
#pragma unroll
    for (int i = 0; i < 8; ++i) {
        float2 v = upk2(acc[i]);
        g_in1[t][(j0 + 2 * i) * BB + b]     = v.x;
        g_in1[t][(j0 + 2 * i + 1) * BB + b] = v.y;
    }
}

// ---------------------------------------------------------------------------
__global__ void k_logits(const float* __restrict__ w_fc,
                         const float* __restrict__ b_fc,
                         float* __restrict__ out) {
    int bid = blockIdx.x;
    int t   = bid >> 2;
    int vb  = bid & 3;
    int tid = threadIdx.x;
    int b   = tid & 63;
    int vs  = tid >> 6;
    int v0  = vb * 64 + vs * 16;

    ull acc[8];
    const ulonglong2* bp = reinterpret_cast<const ulonglong2*>(b_fc + v0);
#pragma unroll
    for (int i = 0; i < 4; ++i) {
        ulonglong2 bq = bp[i];
        acc[2 * i] = bq.x; acc[2 * i + 1] = bq.y;
    }

    const float* o = g_out1[t];
#pragma unroll 2
    for (int h = 0; h < HH; ++h) {
        ull svp = pkd(o[h * BB + b]);
        const ulonglong2* wr = reinterpret_cast<const ulonglong2*>(w_fc + (size_t)h * VV + v0);
        ulonglong2 q0 = wr[0], q1 = wr[1], q2 = wr[2], q3 = wr[3];
        acc[0] = fma2(svp, q0.x, acc[0]);  acc[1] = fma2(svp, q0.y, acc[1]);
        acc[2] = fma2(svp, q1.x, acc[2]);  acc[3] = fma2(svp, q1.y, acc[3]);
        acc[4] = fma2(svp, q2.x, acc[4]);  acc[5] = fma2(svp, q2.y, acc[5]);
        acc[6] = fma2(svp, q3.x, acc[6]);  acc[7] = fma2(svp, q3.y, acc[7]);
    }

    ull* dst = reinterpret_cast<ull*>(out + ((size_t)(t * BB + b)) * VV + v0);
#pragma unroll
    for (int i = 0; i < 8; ++i) dst[i] = acc[i];
}

// ---------------------------------------------------------------------------
// s_final[l][b][h] from g_stateA in [kp][b][2] layout
// ---------------------------------------------------------------------------
__global__ void k_sfinal(float* __restrict__ out, int l) {
    int idx = blockIdx.x * blockDim.x + threadIdx.x;
    if (idx >= BB * HH) return;
    int b = idx >> 9;
    int h = idx & 511;
    out[(size_t)TT * BB * VV + (size_t)l * BB * HH + idx] =
        g_stateA[(h >> 1) * 128 + b * 2 + (h & 1)];
}

// ---------------------------------------------------------------------------
extern "C" void kernel_launch(void* const* d_in, const int* in_sizes, int n_in,
                              void* d_out, int out_size) {
    const int*   x    = (const int*)  d_in[0];
    const float* emb  = (const float*)d_in[1];
    const float* w_in = (const float*)d_in[2];
    const float* w_h  = (const float*)d_in[3];
    const float* b_h  = (const float*)d_in[4];
    const float* w_fc = (const float*)d_in[5];
    const float* b_fc = (const float*)d_in[6];
    float* out = (float*)d_out;

    const int smem_bytes = 131072 + 65536 + 28672;   // 225280 B
    static bool attr_done = false;
    if (!attr_done) {
        cudaFuncSetAttribute(k_rhn<0>, cudaFuncAttributeMaxDynamicSharedMemorySize, smem_bytes);
        cudaFuncSetAttribute(k_rhn<1>, cudaFuncAttributeMaxDynamicSharedMemorySize, smem_bytes);
        attr_done = true;
    }

    const bool has_sfinal = (out_size >= TT * BB * VV + 2 * BB * HH);

    k_reset<<<2, 256>>>();                                              // 1
    k_table<<<VV, 256>>>(emb, w_in);                                    // 2
    k_zero<<<(256 * BB * 2 + 255) / 256, 256>>>();                      // 3
    k_rhn<0><<<GRID_REC, NTH, smem_bytes>>>(x, w_h, b_h);               // 4 <- profiled
    if (has_sfinal)
        k_sfinal<<<(BB * HH + 255) / 256, 256>>>(out, 0);
    k_inp1<<<TT * 16, 256>>>(w_in);
    k_zero<<<(256 * BB * 2 + 255) / 256, 256>>>();
    k_rhn<1><<<GRID_REC, NTH, smem_bytes>>>(x, w_h, b_h);
    k_logits<<<TT * 4, 256>>>(w_fc, b_fc, out);
    if (has_sfinal)
        k_sfinal<<<(BB * HH + 255) / 256, 256>>>(out, 1);
}